// round 11
// baseline (speedup 1.0000x reference)
#include <cuda_runtime.h>
#include <cuda_bf16.h>
#include <cuda_fp16.h>
#include <math.h>
#include <cstdint>

#define TOTE (4096 * 768)
#define WELE (768 * 768)
#define AST 72     // bf16 smem row stride for 64-wide tiles (144B)
#define BST 40     // bf16 smem row stride for 32-wide K-chunks (80B; 5x16B units mod 8 -> conflict-free ldsm)
#define WSTW 36    // W fp32 smem row stride (144B)

// Scratch (allocation-free rule: __device__ globals)
__device__ __nv_bfloat16 g_ahi[TOTE];        // activation split (query, then att out)
__device__ __nv_bfloat16 g_alo[TOTE];
__device__ __nv_bfloat16 g_whi[4 * WELE];    // Wq|Wk|Wv|Wo hi
__device__ __nv_bfloat16 g_wlo[4 * WELE];
__device__ __nv_bfloat16 g_qkh[2 * TOTE];    // Q|K hi
__device__ __nv_bfloat16 g_qkl[2 * TOTE];    // Q|K lo
__device__ __half        g_vf[TOTE];         // V fp16

// ===========================================================================
// Base-sm_103-safe helpers (no tcgen05: ptxas virtual target is compute_103)
// ===========================================================================
__device__ __forceinline__ uint32_t smem_u32(const void* p) {
    uint32_t a;
    asm("{ .reg .u64 t; cvta.to.shared.u64 t, %1; cvt.u32.u64 %0, t; }" : "=r"(a) : "l"(p));
    return a;
}
__device__ __forceinline__ void ldsm_x4(uint32_t* r, uint32_t addr) {
    asm volatile("ldmatrix.sync.aligned.m8n8.x4.shared.b16 {%0,%1,%2,%3}, [%4];"
                 : "=r"(r[0]), "=r"(r[1]), "=r"(r[2]), "=r"(r[3]) : "r"(addr));
}
__device__ __forceinline__ void ldsm_x4_t(uint32_t* r, uint32_t addr) {
    asm volatile("ldmatrix.sync.aligned.m8n8.x4.trans.shared.b16 {%0,%1,%2,%3}, [%4];"
                 : "=r"(r[0]), "=r"(r[1]), "=r"(r[2]), "=r"(r[3]) : "r"(addr));
}
__device__ __forceinline__ void mma_bf(float* d, const uint32_t* a, uint32_t b0, uint32_t b1) {
    asm volatile(
        "mma.sync.aligned.m16n8k16.row.col.f32.bf16.bf16.f32 "
        "{%0,%1,%2,%3}, {%4,%5,%6,%7}, {%8,%9}, {%0,%1,%2,%3};"
        : "+f"(d[0]), "+f"(d[1]), "+f"(d[2]), "+f"(d[3])
        : "r"(a[0]), "r"(a[1]), "r"(a[2]), "r"(a[3]), "r"(b0), "r"(b1));
}
__device__ __forceinline__ void mma_f16(float* d, const uint32_t* a, uint32_t b0, uint32_t b1) {
    asm volatile(
        "mma.sync.aligned.m16n8k16.row.col.f32.f16.f16.f32 "
        "{%0,%1,%2,%3}, {%4,%5,%6,%7}, {%8,%9}, {%0,%1,%2,%3};"
        : "+f"(d[0]), "+f"(d[1]), "+f"(d[2]), "+f"(d[3])
        : "r"(a[0]), "r"(a[1]), "r"(a[2]), "r"(a[3]), "r"(b0), "r"(b1));
}
__device__ __forceinline__ uint32_t pack_f16x2(float lo, float hi) {
    uint32_t d;
    asm("cvt.rn.f16x2.f32 %0, %1, %2;" : "=r"(d) : "f"(hi), "f"(lo));
    return d;
}
__device__ __forceinline__ void cpa16(uint32_t dst, const void* src) {
    asm volatile("cp.async.cg.shared.global [%0], [%1], 16;" :: "r"(dst), "l"(src) : "memory");
}

// ===========================================================================
// fp32 -> bf16 hi/lo splits
// ===========================================================================
__global__ __launch_bounds__(256) void split_f32(
    const float4* __restrict__ x, uint2* __restrict__ hi, uint2* __restrict__ lo, int n4)
{
    int i = blockIdx.x * blockDim.x + threadIdx.x;
    if (i >= n4) return;
    float4 v = x[i];
    float vv[4] = {v.x, v.y, v.z, v.w};
    __nv_bfloat16 h[4], l[4];
#pragma unroll
    for (int j = 0; j < 4; j++) {
        h[j] = __float2bfloat16(vv[j]);
        l[j] = __float2bfloat16(vv[j] - __bfloat162float(h[j]));
    }
    hi[i] = *(uint2*)h;
    lo[i] = *(uint2*)l;
}

__global__ __launch_bounds__(256) void split_w(
    const float4* __restrict__ w0, const float4* __restrict__ w1,
    const float4* __restrict__ w2, const float4* __restrict__ w3,
    uint2* __restrict__ hi, uint2* __restrict__ lo)
{
    const int z = blockIdx.y;
    const float4* src = (z == 0) ? w0 : (z == 1) ? w1 : (z == 2) ? w2 : w3;
    int i = blockIdx.x * blockDim.x + threadIdx.x;
    if (i >= WELE / 4) return;
    float4 v = src[i];
    float vv[4] = {v.x, v.y, v.z, v.w};
    __nv_bfloat16 h[4], l[4];
#pragma unroll
    for (int j = 0; j < 4; j++) {
        h[j] = __float2bfloat16(vv[j]);
        l[j] = __float2bfloat16(vv[j] - __bfloat162float(h[j]));
    }
    hi[(size_t)z * (WELE / 4) + i] = *(uint2*)h;
    lo[(size_t)z * (WELE / 4) + i] = *(uint2*)l;
}

// ===========================================================================
// HMMA split-bf16 NT GEMM v3: block tile 128x128 (halves L2 traffic vs
// 128x64), K-chunk 32, 2-stage cp.async, ONE barrier per chunk, 2 CTAs/SM.
// 8 warps = 4m x 2n, warp tile 32x64.
// ===========================================================================
#define GTC (128 * BST * 2)          // bytes per array per stage (10240)
#define GSTB (4 * GTC)               // stage stride (40960)

__global__ __launch_bounds__(256, 2) void gemm_mma(
    const __nv_bfloat16* __restrict__ Ahi, const __nv_bfloat16* __restrict__ Alo,
    const __nv_bfloat16* __restrict__ Whi, const __nv_bfloat16* __restrict__ Wlo,
    const float* __restrict__ bias, float* __restrict__ Cf,
    __nv_bfloat16* __restrict__ Chi, __nv_bfloat16* __restrict__ Clo,
    __half* __restrict__ Cf16, int wbase)
{
    extern __shared__ __align__(16) __nv_bfloat16 smb[];
    const uint32_t sb = smem_u32(smb);

    const int tid = threadIdx.x, wid = tid >> 5, lane = tid & 31;
    const int wm = (wid >> 1) * 32, wn = (wid & 1) * 64;
    const int m0 = blockIdx.y * 128, n0 = blockIdx.x * 128;
    const int z = blockIdx.z;

    const __nv_bfloat16* gAh = Ahi + (size_t)m0 * 768;
    const __nv_bfloat16* gAl = Alo + (size_t)m0 * 768;
    const __nv_bfloat16* gBh = Whi + (size_t)(wbase + z) * WELE + (size_t)n0 * 768;
    const __nv_bfloat16* gBl = Wlo + (size_t)(wbase + z) * WELE + (size_t)n0 * 768;

    float acc[2][8][4];
#pragma unroll
    for (int i = 0; i < 2; i++)
#pragma unroll
        for (int j = 0; j < 8; j++)
#pragma unroll
            for (int k = 0; k < 4; k++) acc[i][j][k] = 0.f;

#define GSTAGE(buf, c_)                                                        \
    {                                                                          \
        uint32_t base_ = sb + (buf) * GSTB;                                    \
        const int k0_ = (c_) * 32;                                             \
        _Pragma("unroll")                                                      \
        for (int it = 0; it < 2; it++) {                                       \
            int idx = it * 256 + tid;                                          \
            int row = idx >> 2, cc = idx & 3;                                  \
            uint32_t off = (uint32_t)(row * BST + cc * 8) * 2;                 \
            size_t go = (size_t)row * 768 + k0_ + cc * 8;                      \
            cpa16(base_ + off,           gAh + go);                            \
            cpa16(base_ + GTC + off,     gAl + go);                            \
            cpa16(base_ + 2 * GTC + off, gBh + go);                            \
            cpa16(base_ + 3 * GTC + off, gBl + go);                            \
        }                                                                      \
        asm volatile("cp.async.commit_group;" ::: "memory");                   \
    }

    GSTAGE(0, 0);

    const int lrow = lane & 15, lcol8 = (lane >> 4) * 8;
    const uint32_t offA = (uint32_t)((wm + lrow) * BST + lcol8) * 2;
    const uint32_t offB = (uint32_t)((wn + lrow) * BST + lcol8) * 2;

    for (int c = 0; c < 24; c++) {
        asm volatile("cp.async.wait_group 0;" ::: "memory");
        __syncthreads();
        if (c + 1 < 24) GSTAGE((c + 1) & 1, c + 1);   // writes buf read at c-1: safe after sync
        uint32_t base = sb + (c & 1) * GSTB;
        uint32_t aAh = base + offA, aAl = base + GTC + offA;
        uint32_t aBh = base + 2 * GTC + offB, aBl = base + 3 * GTC + offB;
#pragma unroll
        for (int kk = 0; kk < 2; kk++) {
            const uint32_t koff = kk * 32;   // 16 elements * 2B
            uint32_t ah[2][4], al[2][4];
#pragma unroll
            for (int mf = 0; mf < 2; mf++) {
                ldsm_x4(ah[mf], aAh + mf * 16 * BST * 2 + koff);
                ldsm_x4(al[mf], aAl + mf * 16 * BST * 2 + koff);
            }
#pragma unroll
            for (int nq = 0; nq < 4; nq++) {
                uint32_t bh[4], bl[4];                      // short live range
                ldsm_x4(bh, aBh + nq * 16 * BST * 2 + koff);
                ldsm_x4(bl, aBl + nq * 16 * BST * 2 + koff);
#pragma unroll
                for (int mf = 0; mf < 2; mf++) {
                    float* a0 = acc[mf][nq * 2 + 0];
                    float* a1 = acc[mf][nq * 2 + 1];
                    mma_bf(a0, ah[mf], bh[0], bh[2]);
                    mma_bf(a1, ah[mf], bh[1], bh[3]);
                    mma_bf(a0, al[mf], bh[0], bh[2]);
                    mma_bf(a1, al[mf], bh[1], bh[3]);
                    mma_bf(a0, ah[mf], bl[0], bl[2]);
                    mma_bf(a1, ah[mf], bl[1], bl[3]);
                }
            }
        }
    }

#pragma unroll
    for (int mf = 0; mf < 2; mf++) {
#pragma unroll
        for (int nf = 0; nf < 8; nf++) {
            int row = m0 + wm + mf * 16 + (lane >> 2);
            int col = n0 + wn + nf * 8 + (lane & 3) * 2;
            float v0 = acc[mf][nf][0], v1 = acc[mf][nf][1];
            float v2 = acc[mf][nf][2], v3 = acc[mf][nf][3];
            if (Cf) {
                float b0 = bias[col], b1 = bias[col + 1];
                *(float2*)(Cf + (size_t)row * 768 + col) = make_float2(v0 + b0, v1 + b1);
                *(float2*)(Cf + (size_t)(row + 8) * 768 + col) = make_float2(v2 + b0, v3 + b1);
            } else if (z == 2) {
                __half2 h0 = __floats2half2_rn(v0, v1);
                __half2 h1 = __floats2half2_rn(v2, v3);
                *(uint32_t*)(Cf16 + (size_t)row * 768 + col) = *(uint32_t*)&h0;
                *(uint32_t*)(Cf16 + (size_t)(row + 8) * 768 + col) = *(uint32_t*)&h1;
            } else {
                __nv_bfloat16* ch = Chi + (size_t)z * TOTE;
                __nv_bfloat16* cl = Clo + (size_t)z * TOTE;
                __nv_bfloat16 h0 = __float2bfloat16(v0), h1 = __float2bfloat16(v1);
                __nv_bfloat16 h2 = __float2bfloat16(v2), h3 = __float2bfloat16(v3);
                __nv_bfloat162 ph0 = {h0, h1}, ph1 = {h2, h3};
                __nv_bfloat162 pl0 = {__float2bfloat16(v0 - __bfloat162float(h0)),
                                      __float2bfloat16(v1 - __bfloat162float(h1))};
                __nv_bfloat162 pl1 = {__float2bfloat16(v2 - __bfloat162float(h2)),
                                      __float2bfloat16(v3 - __bfloat162float(h3))};
                *(uint32_t*)(ch + (size_t)row * 768 + col) = *(uint32_t*)&ph0;
                *(uint32_t*)(ch + (size_t)(row + 8) * 768 + col) = *(uint32_t*)&ph1;
                *(uint32_t*)(cl + (size_t)row * 768 + col) = *(uint32_t*)&pl0;
                *(uint32_t*)(cl + (size_t)(row + 8) * 768 + col) = *(uint32_t*)&pl1;
            }
        }
    }
}

// ===========================================================================
// HMMA fused biased flash attention, v5: NO online max.
// Logits = W + 0.125*(q.k) are bounded (|logit| <~ 7; overflow needs >88),
// and softmax is shift-invariant, so exp() is taken directly. This removes
// the per-tile max shuffles, correction exps, and accumulator rescales —
// the entire serial softmax dependency chain.
// Key tile 32, 3-stage cp.async pipeline (K hi/lo + V + W), 2 CTAs/SM.
// ===========================================================================
#define KT 32
#define KVB (KT * AST * 2)            // 4608 B per K/V array per stage
#define WB  (128 * WSTW * 4)          // 18432 B W tile per stage
#define STB (3 * KVB + WB)            // stage stride 32256 B

__global__ __launch_bounds__(256, 2) void attn_mma(
    const __nv_bfloat16* __restrict__ qkh, const __nv_bfloat16* __restrict__ qkl,
    const __half* __restrict__ vf, const float* __restrict__ W,
    __nv_bfloat16* __restrict__ ohi, __nv_bfloat16* __restrict__ olo)
{
    extern __shared__ __align__(16) char smn[];
    const uint32_t sb = smem_u32(smn);

    const int tid = threadIdx.x, wp = tid >> 5, lane = tid & 31;
    const int n0 = blockIdx.x * 128, h = blockIdx.y, b = blockIdx.z;

    const __nv_bfloat16* qh = qkh + ((size_t)(b * 1024 + n0)) * 768 + h * 64;
    const __nv_bfloat16* ql = qkl + ((size_t)(b * 1024 + n0)) * 768 + h * 64;
    const __nv_bfloat16* kh = qkh + (size_t)TOTE + (size_t)b * 1024 * 768 + h * 64;
    const __nv_bfloat16* kl = qkl + (size_t)TOTE + (size_t)b * 1024 * 768 + h * 64;
    const __half* vg = vf + (size_t)b * 1024 * 768 + h * 64;
    const float* wg = W + ((size_t)(b * 12 + h) * 1024 + n0) * 1024;

    // --- Stage Q (128x64) hi/lo through smem (pre-pipeline), frags to regs ---
    {
        __nv_bfloat16* tQh = (__nv_bfloat16*)smn;
        __nv_bfloat16* tQl = tQh + 128 * AST;
#pragma unroll
        for (int it = 0; it < 4; it++) {
            int idx = it * 256 + tid;
            int row = idx >> 3, cc = idx & 7;
            *(uint4*)(tQh + row * AST + cc * 8) = *(const uint4*)(qh + (size_t)row * 768 + cc * 8);
            *(uint4*)(tQl + row * AST + cc * 8) = *(const uint4*)(ql + (size_t)row * 768 + cc * 8);
        }
    }
    __syncthreads();
    uint32_t qfh[4][4], qfl[4][4];
    {
        uint32_t off = (uint32_t)((wp * 16 + (lane & 15)) * AST + (lane >> 4) * 8) * 2;
#pragma unroll
        for (int ks = 0; ks < 4; ks++) {
            ldsm_x4(qfh[ks], sb + off + ks * 32);
            ldsm_x4(qfl[ks], sb + 128 * AST * 2 + off + ks * 32);
        }
    }
    __syncthreads();

    float oacc[8][4];
#pragma unroll
    for (int d = 0; d < 8; d++)
#pragma unroll
        for (int j = 0; j < 4; j++) oacc[d][j] = 0.f;
    float l0r = 0.f, l1r = 0.f;

#define ASTAGE(buf, t_)                                                        \
    {                                                                          \
        uint32_t base_ = sb + (buf) * STB;                                     \
        const int s0_ = (t_) * KT;                                             \
        {                                                                      \
            int row = tid >> 3, cc = tid & 7;                                  \
            uint32_t doff = (uint32_t)(row * AST + cc * 8) * 2;                \
            size_t go = (size_t)(s0_ + row) * 768 + cc * 8;                    \
            cpa16(base_ + doff,           kh + go);                            \
            cpa16(base_ + KVB + doff,     kl + go);                            \
            cpa16(base_ + 2 * KVB + doff, vg + go);                            \
        }                                                                      \
        _Pragma("unroll")                                                      \
        for (int it = 0; it < 4; it++) {                                       \
            int idx = it * 256 + tid;                                          \
            int row = idx >> 3, cc = idx & 7;                                  \
            cpa16(base_ + 3 * KVB + (uint32_t)(row * WSTW + cc * 4) * 4,       \
                  wg + (size_t)row * 1024 + s0_ + cc * 4);                     \
        }                                                                      \
        asm volatile("cp.async.commit_group;" ::: "memory");                   \
    }

    ASTAGE(0, 0); ASTAGE(1, 1);

    const uint32_t foff = (uint32_t)(((lane & 15) * AST) + (lane >> 4) * 8) * 2;
    const int c0 = (lane & 3) * 2;
    const uint32_t woff = (uint32_t)((wp * 16 + (lane >> 2)) * WSTW + c0) * 4;

    for (int t = 0; t < 32; t++) {
        if (t + 2 < 32) {
            asm volatile("cp.async.wait_group 1;" ::: "memory");
        } else {
            asm volatile("cp.async.wait_group 0;" ::: "memory");
        }
        __syncthreads();
        if (t + 2 < 32) ASTAGE((t + 2) % 3, t + 2);   // writes stage read at t-1: safe after sync
        uint32_t base = sb + (t % 3) * STB;
        uint32_t kbh = base + foff, kbl = base + KVB + foff;
        uint32_t vbb = base + 2 * KVB + foff;
        uint32_t wb0 = base + 3 * KVB + woff;

        // ---- S = Q K^T (3-term split-bf16), 32 keys ----
        float sc[4][4];
#pragma unroll
        for (int nf = 0; nf < 4; nf++)
#pragma unroll
            for (int j = 0; j < 4; j++) sc[nf][j] = 0.f;
#pragma unroll
        for (int nf2 = 0; nf2 < 2; nf2++) {
#pragma unroll
            for (int ks = 0; ks < 4; ks++) {
                uint32_t off = (uint32_t)(nf2 * 16 * AST + ks * 16) * 2;
                uint32_t fh[4], fl[4];
                ldsm_x4(fh, kbh + off);
                ldsm_x4(fl, kbl + off);
                mma_bf(sc[2 * nf2],     qfh[ks], fh[0], fh[2]);
                mma_bf(sc[2 * nf2 + 1], qfh[ks], fh[1], fh[3]);
                mma_bf(sc[2 * nf2],     qfl[ks], fh[0], fh[2]);
                mma_bf(sc[2 * nf2 + 1], qfl[ks], fh[1], fh[3]);
                mma_bf(sc[2 * nf2],     qfh[ks], fl[0], fl[2]);
                mma_bf(sc[2 * nf2 + 1], qfh[ks], fl[1], fl[3]);
            }
        }

        // ---- p = exp(W + scale*S) directly (bounded logits, no max) ----
        float rs0 = 0.f, rs1 = 0.f;
#pragma unroll
        for (int nf = 0; nf < 4; nf++) {
            float2 w0, w1;
            asm volatile("ld.shared.v2.f32 {%0,%1}, [%2];"
                         : "=f"(w0.x), "=f"(w0.y) : "r"(wb0 + nf * 32));
            asm volatile("ld.shared.v2.f32 {%0,%1}, [%2];"
                         : "=f"(w1.x), "=f"(w1.y) : "r"(wb0 + 8 * WSTW * 4 + nf * 32));
            sc[nf][0] = __expf(fmaf(sc[nf][0], 0.125f, w0.x));
            sc[nf][1] = __expf(fmaf(sc[nf][1], 0.125f, w0.y));
            sc[nf][2] = __expf(fmaf(sc[nf][2], 0.125f, w1.x));
            sc[nf][3] = __expf(fmaf(sc[nf][3], 0.125f, w1.y));
            rs0 += sc[nf][0] + sc[nf][1];
            rs1 += sc[nf][2] + sc[nf][3];
        }
        l0r += rs0;
        l1r += rs1;

        // ---- out += P V (fp16, P from registers; no rescale needed) ----
#pragma unroll
        for (int kc = 0; kc < 2; kc++) {
            uint32_t pa[4];
            pa[0] = pack_f16x2(sc[2 * kc][0], sc[2 * kc][1]);
            pa[1] = pack_f16x2(sc[2 * kc][2], sc[2 * kc][3]);
            pa[2] = pack_f16x2(sc[2 * kc + 1][0], sc[2 * kc + 1][1]);
            pa[3] = pack_f16x2(sc[2 * kc + 1][2], sc[2 * kc + 1][3]);
#pragma unroll
            for (int dp = 0; dp < 4; dp++) {
                uint32_t vf4[4];
                ldsm_x4_t(vf4, vbb + (uint32_t)(kc * 16 * AST + dp * 16) * 2);
                mma_f16(oacc[2 * dp],     pa, vf4[0], vf4[1]);
                mma_f16(oacc[2 * dp + 1], pa, vf4[2], vf4[3]);
            }
        }
    }

    // ---- normalize + write bf16 hi/lo (att layout [4096, 768]) ----
    l0r += __shfl_xor_sync(0xffffffffu, l0r, 1);
    l0r += __shfl_xor_sync(0xffffffffu, l0r, 2);
    l1r += __shfl_xor_sync(0xffffffffu, l1r, 1);
    l1r += __shfl_xor_sync(0xffffffffu, l1r, 2);
    float i0 = 1.f / l0r, i1 = 1.f / l1r;
    int row = b * 1024 + n0 + wp * 16 + (lane >> 2);
    int colb = h * 64 + c0;
#pragma unroll
    for (int d = 0; d < 8; d++) {
        float v0 = oacc[d][0] * i0, v1 = oacc[d][1] * i0;
        float v2 = oacc[d][2] * i1, v3 = oacc[d][3] * i1;
        __nv_bfloat16 h0 = __float2bfloat16(v0), h1 = __float2bfloat16(v1);
        __nv_bfloat16 h2 = __float2bfloat16(v2), h3 = __float2bfloat16(v3);
        __nv_bfloat162 ph0 = {h0, h1}, ph1 = {h2, h3};
        __nv_bfloat162 pl0 = {__float2bfloat16(v0 - __bfloat162float(h0)),
                              __float2bfloat16(v1 - __bfloat162float(h1))};
        __nv_bfloat162 pl1 = {__float2bfloat16(v2 - __bfloat162float(h2)),
                              __float2bfloat16(v3 - __bfloat162float(h3))};
        *(uint32_t*)(ohi + (size_t)row * 768 + colb + d * 8) = *(uint32_t*)&ph0;
        *(uint32_t*)(ohi + (size_t)(row + 8) * 768 + colb + d * 8) = *(uint32_t*)&ph1;
        *(uint32_t*)(olo + (size_t)row * 768 + colb + d * 8) = *(uint32_t*)&pl0;
        *(uint32_t*)(olo + (size_t)(row + 8) * 768 + colb + d * 8) = *(uint32_t*)&pl1;
    }
}

// ===========================================================================
// Launch
// ===========================================================================
extern "C" void kernel_launch(void* const* d_in, const int* in_sizes, int n_in,
                              void* d_out, int out_size)
{
    const float* query = (const float*)d_in[0];
    const float* attw  = (const float*)d_in[1];
    const float* Wq    = (const float*)d_in[2];
    const float* Wk    = (const float*)d_in[3];
    const float* Wv    = (const float*)d_in[4];
    const float* Wo    = (const float*)d_in[5];
    const float* bo    = (const float*)d_in[6];
    float* out = (float*)d_out;

    __nv_bfloat16 *ahi, *alo, *whi, *wlo, *qkh, *qkl;
    __half* vfp;
    cudaGetSymbolAddress((void**)&ahi, g_ahi);
    cudaGetSymbolAddress((void**)&alo, g_alo);
    cudaGetSymbolAddress((void**)&whi, g_whi);
    cudaGetSymbolAddress((void**)&wlo, g_wlo);
    cudaGetSymbolAddress((void**)&qkh, g_qkh);
    cudaGetSymbolAddress((void**)&qkl, g_qkl);
    cudaGetSymbolAddress((void**)&vfp, g_vf);

    const int gemm_smem = 2 * GSTB;                // 81920 (2 CTAs/SM)
    cudaFuncSetAttribute(gemm_mma, cudaFuncAttributeMaxDynamicSharedMemorySize, gemm_smem);
    const int attn_smem = 3 * STB;                 // 96768 (2 CTAs/SM)
    cudaFuncSetAttribute(attn_mma, cudaFuncAttributeMaxDynamicSharedMemorySize, attn_smem);

    // 1) Split query + all four weights
    split_f32<<<TOTE / 4 / 256, 256>>>((const float4*)query, (uint2*)ahi, (uint2*)alo, TOTE / 4);
    split_w<<<dim3(WELE / 4 / 256, 4), 256>>>((const float4*)Wq, (const float4*)Wk,
                                              (const float4*)Wv, (const float4*)Wo,
                                              (uint2*)whi, (uint2*)wlo);

    // 2) QKV: z<2 -> Q/K bf16 hi/lo, z==2 -> V fp16
    gemm_mma<<<dim3(6, 32, 3), 256, gemm_smem>>>(ahi, alo, whi, wlo,
                                                 nullptr, nullptr, qkh, qkl, vfp, 0);

    // 3) Fused biased attention; att hi/lo -> ahi/alo
    attn_mma<<<dim3(8, 12, 4), 256, attn_smem>>>(qkh, qkl, vfp, attw, ahi, alo);

    // 4) Output projection (fp32 + bias)
    gemm_mma<<<dim3(6, 32, 1), 256, gemm_smem>>>(ahi, alo, whi, wlo,
                                                 bo, out, nullptr, nullptr, nullptr, 3);
}

// round 12
// speedup vs baseline: 1.1632x; 1.1632x over previous
#include <cuda_runtime.h>
#include <cuda_bf16.h>
#include <cuda_fp16.h>
#include <math.h>
#include <cstdint>

#define TOTE (4096 * 768)
#define WELE (768 * 768)
#define AST 72     // bf16/fp16 smem row stride for 64-wide tiles (144B)
#define WSTW 36    // W fp32 smem row stride (144B)

// Scratch (allocation-free rule: __device__ globals)
__device__ __nv_bfloat16 g_ahi[TOTE];        // query hi
__device__ __nv_bfloat16 g_alo[TOTE];        // query lo
__device__ __half        g_qf16[TOTE];       // query fp16 (for V projection)
__device__ __nv_bfloat16 g_whi[2 * WELE];    // Wq|Wk hi
__device__ __nv_bfloat16 g_wlo[2 * WELE];    // Wq|Wk lo
__device__ __half        g_wf16[2 * WELE];   // Wv|Wo fp16
__device__ __nv_bfloat16 g_qkh[2 * TOTE];    // Q|K hi
__device__ __nv_bfloat16 g_qkl[2 * TOTE];    // Q|K lo
__device__ __half        g_vf[TOTE];         // V fp16
__device__ __half        g_att16[TOTE];      // attention output fp16

// ===========================================================================
// Base-sm_103-safe helpers (no tcgen05: ptxas virtual target is compute_103)
// ===========================================================================
__device__ __forceinline__ uint32_t smem_u32(const void* p) {
    uint32_t a;
    asm("{ .reg .u64 t; cvta.to.shared.u64 t, %1; cvt.u32.u64 %0, t; }" : "=r"(a) : "l"(p));
    return a;
}
__device__ __forceinline__ void ldsm_x4(uint32_t* r, uint32_t addr) {
    asm volatile("ldmatrix.sync.aligned.m8n8.x4.shared.b16 {%0,%1,%2,%3}, [%4];"
                 : "=r"(r[0]), "=r"(r[1]), "=r"(r[2]), "=r"(r[3]) : "r"(addr));
}
__device__ __forceinline__ void ldsm_x4_t(uint32_t* r, uint32_t addr) {
    asm volatile("ldmatrix.sync.aligned.m8n8.x4.trans.shared.b16 {%0,%1,%2,%3}, [%4];"
                 : "=r"(r[0]), "=r"(r[1]), "=r"(r[2]), "=r"(r[3]) : "r"(addr));
}
__device__ __forceinline__ void mma_bf(float* d, const uint32_t* a, uint32_t b0, uint32_t b1) {
    asm volatile(
        "mma.sync.aligned.m16n8k16.row.col.f32.bf16.bf16.f32 "
        "{%0,%1,%2,%3}, {%4,%5,%6,%7}, {%8,%9}, {%0,%1,%2,%3};"
        : "+f"(d[0]), "+f"(d[1]), "+f"(d[2]), "+f"(d[3])
        : "r"(a[0]), "r"(a[1]), "r"(a[2]), "r"(a[3]), "r"(b0), "r"(b1));
}
__device__ __forceinline__ void mma_f16(float* d, const uint32_t* a, uint32_t b0, uint32_t b1) {
    asm volatile(
        "mma.sync.aligned.m16n8k16.row.col.f32.f16.f16.f32 "
        "{%0,%1,%2,%3}, {%4,%5,%6,%7}, {%8,%9}, {%0,%1,%2,%3};"
        : "+f"(d[0]), "+f"(d[1]), "+f"(d[2]), "+f"(d[3])
        : "r"(a[0]), "r"(a[1]), "r"(a[2]), "r"(a[3]), "r"(b0), "r"(b1));
}
__device__ __forceinline__ uint32_t pack_f16x2(float lo, float hi) {
    uint32_t d;
    asm("cvt.rn.f16x2.f32 %0, %1, %2;" : "=r"(d) : "f"(hi), "f"(lo));
    return d;
}
__device__ __forceinline__ void cpa16(uint32_t dst, const void* src) {
    asm volatile("cp.async.cg.shared.global [%0], [%1], 16;" :: "r"(dst), "l"(src) : "memory");
}

// ===========================================================================
// Conversions
// ===========================================================================
// query: fp32 -> bf16 hi/lo + fp16
__global__ __launch_bounds__(256) void split_q(
    const float4* __restrict__ x, uint2* __restrict__ hi, uint2* __restrict__ lo,
    uint2* __restrict__ f16, int n4)
{
    int i = blockIdx.x * blockDim.x + threadIdx.x;
    if (i >= n4) return;
    float4 v = x[i];
    float vv[4] = {v.x, v.y, v.z, v.w};
    __nv_bfloat16 h[4], l[4];
    __half f[4];
#pragma unroll
    for (int j = 0; j < 4; j++) {
        h[j] = __float2bfloat16(vv[j]);
        l[j] = __float2bfloat16(vv[j] - __bfloat162float(h[j]));
        f[j] = __float2half_rn(vv[j]);
    }
    hi[i] = *(uint2*)h;
    lo[i] = *(uint2*)l;
    f16[i] = *(uint2*)f;
}

// Wq|Wk: fp32 -> bf16 hi/lo (z selects)
__global__ __launch_bounds__(256) void split_w(
    const float4* __restrict__ w0, const float4* __restrict__ w1,
    uint2* __restrict__ hi, uint2* __restrict__ lo)
{
    const int z = blockIdx.y;
    const float4* src = (z == 0) ? w0 : w1;
    int i = blockIdx.x * blockDim.x + threadIdx.x;
    if (i >= WELE / 4) return;
    float4 v = src[i];
    float vv[4] = {v.x, v.y, v.z, v.w};
    __nv_bfloat16 h[4], l[4];
#pragma unroll
    for (int j = 0; j < 4; j++) {
        h[j] = __float2bfloat16(vv[j]);
        l[j] = __float2bfloat16(vv[j] - __bfloat162float(h[j]));
    }
    hi[(size_t)z * (WELE / 4) + i] = *(uint2*)h;
    lo[(size_t)z * (WELE / 4) + i] = *(uint2*)l;
}

// Wv|Wo: fp32 -> fp16 (z selects)
__global__ __launch_bounds__(256) void conv_w16(
    const float4* __restrict__ w0, const float4* __restrict__ w1, uint2* __restrict__ f16)
{
    const int z = blockIdx.y;
    const float4* src = (z == 0) ? w0 : w1;
    int i = blockIdx.x * blockDim.x + threadIdx.x;
    if (i >= WELE / 4) return;
    float4 v = src[i];
    __half f[4] = {__float2half_rn(v.x), __float2half_rn(v.y),
                   __float2half_rn(v.z), __float2half_rn(v.w)};
    f16[(size_t)z * (WELE / 4) + i] = *(uint2*)f;
}

// ===========================================================================
// HMMA split-bf16 NT GEMM (Q,K projections): block tile 128x64, K-chunk 64,
// 2-stage cp.async, ONE barrier per chunk, 2 CTAs/SM. Epilogue: bf16 hi/lo.
// ===========================================================================
#define GTA (128 * AST * 2)          // A array bytes/stage (18432)
#define GTB (64 * AST * 2)           // B array bytes/stage (9216)
#define GSTB (2 * GTA + 2 * GTB)     // stage stride (55296)

__global__ __launch_bounds__(256, 2) void gemm_bf3(
    const __nv_bfloat16* __restrict__ Ahi, const __nv_bfloat16* __restrict__ Alo,
    const __nv_bfloat16* __restrict__ Whi, const __nv_bfloat16* __restrict__ Wlo,
    __nv_bfloat16* __restrict__ Chi, __nv_bfloat16* __restrict__ Clo)
{
    extern __shared__ __align__(16) __nv_bfloat16 smb[];
    const uint32_t sb = smem_u32(smb);

    const int tid = threadIdx.x, wid = tid >> 5, lane = tid & 31;
    const int wm = (wid >> 1) * 32, wn = (wid & 1) * 32;
    const int m0 = blockIdx.y * 128, n0 = blockIdx.x * 64;
    const int z = blockIdx.z;

    const __nv_bfloat16* gAh = Ahi + (size_t)m0 * 768;
    const __nv_bfloat16* gAl = Alo + (size_t)m0 * 768;
    const __nv_bfloat16* gBh = Whi + (size_t)z * WELE + (size_t)n0 * 768;
    const __nv_bfloat16* gBl = Wlo + (size_t)z * WELE + (size_t)n0 * 768;

    float acc[2][4][4];
#pragma unroll
    for (int i = 0; i < 2; i++)
#pragma unroll
        for (int j = 0; j < 4; j++)
#pragma unroll
            for (int k = 0; k < 4; k++) acc[i][j][k] = 0.f;

#define GSTAGE(buf, c_)                                                        \
    {                                                                          \
        uint32_t base_ = sb + (buf) * GSTB;                                    \
        const int k0_ = (c_) * 64;                                             \
        _Pragma("unroll")                                                      \
        for (int it = 0; it < 4; it++) {                                       \
            int idx = it * 256 + tid;                                          \
            int row = idx >> 3, cc = idx & 7;                                  \
            uint32_t off = (uint32_t)(row * AST + cc * 8) * 2;                 \
            size_t go = (size_t)row * 768 + k0_ + cc * 8;                      \
            cpa16(base_ + off,       gAh + go);                                \
            cpa16(base_ + GTA + off, gAl + go);                                \
        }                                                                      \
        _Pragma("unroll")                                                      \
        for (int it = 0; it < 2; it++) {                                       \
            int idx = it * 256 + tid;                                          \
            int row = idx >> 3, cc = idx & 7;                                  \
            uint32_t off = (uint32_t)(row * AST + cc * 8) * 2;                 \
            size_t go = (size_t)row * 768 + k0_ + cc * 8;                      \
            cpa16(base_ + 2 * GTA + off,       gBh + go);                      \
            cpa16(base_ + 2 * GTA + GTB + off, gBl + go);                      \
        }                                                                      \
        asm volatile("cp.async.commit_group;" ::: "memory");                   \
    }

    GSTAGE(0, 0);

    const int lrow = lane & 15, lcol8 = (lane >> 4) * 8;
    const uint32_t offA = (uint32_t)((wm + lrow) * AST + lcol8) * 2;
    const uint32_t offB = (uint32_t)((wn + lrow) * AST + lcol8) * 2;

    for (int c = 0; c < 12; c++) {
        asm volatile("cp.async.wait_group 0;" ::: "memory");
        __syncthreads();
        if (c + 1 < 12) GSTAGE((c + 1) & 1, c + 1);   // writes buf read at c-1
        uint32_t base = sb + (c & 1) * GSTB;
        uint32_t aAh = base + offA, aAl = base + GTA + offA;
        uint32_t aBh = base + 2 * GTA + offB, aBl = base + 2 * GTA + GTB + offB;
#pragma unroll
        for (int kk = 0; kk < 4; kk++) {
            const uint32_t koff = kk * 32;
            uint32_t ah[2][4], al[2][4], bh[2][4], bl[2][4];
#pragma unroll
            for (int mf = 0; mf < 2; mf++) {
                ldsm_x4(ah[mf], aAh + mf * 16 * AST * 2 + koff);
                ldsm_x4(al[mf], aAl + mf * 16 * AST * 2 + koff);
            }
#pragma unroll
            for (int nq = 0; nq < 2; nq++) {
                ldsm_x4(bh[nq], aBh + nq * 16 * AST * 2 + koff);
                ldsm_x4(bl[nq], aBl + nq * 16 * AST * 2 + koff);
            }
#pragma unroll
            for (int mf = 0; mf < 2; mf++) {
#pragma unroll
                for (int nq = 0; nq < 2; nq++) {
                    float* a0 = acc[mf][nq * 2 + 0];
                    float* a1 = acc[mf][nq * 2 + 1];
                    mma_bf(a0, ah[mf], bh[nq][0], bh[nq][2]);
                    mma_bf(a1, ah[mf], bh[nq][1], bh[nq][3]);
                    mma_bf(a0, al[mf], bh[nq][0], bh[nq][2]);
                    mma_bf(a1, al[mf], bh[nq][1], bh[nq][3]);
                    mma_bf(a0, ah[mf], bl[nq][0], bl[nq][2]);
                    mma_bf(a1, ah[mf], bl[nq][1], bl[nq][3]);
                }
            }
        }
    }

#pragma unroll
    for (int mf = 0; mf < 2; mf++) {
#pragma unroll
        for (int nf = 0; nf < 4; nf++) {
            int row = m0 + wm + mf * 16 + (lane >> 2);
            int col = n0 + wn + nf * 8 + (lane & 3) * 2;
            float v0 = acc[mf][nf][0], v1 = acc[mf][nf][1];
            float v2 = acc[mf][nf][2], v3 = acc[mf][nf][3];
            __nv_bfloat16* ch = Chi + (size_t)z * TOTE;
            __nv_bfloat16* cl = Clo + (size_t)z * TOTE;
            __nv_bfloat16 h0 = __float2bfloat16(v0), h1 = __float2bfloat16(v1);
            __nv_bfloat16 h2 = __float2bfloat16(v2), h3 = __float2bfloat16(v3);
            __nv_bfloat162 ph0 = {h0, h1}, ph1 = {h2, h3};
            __nv_bfloat162 pl0 = {__float2bfloat16(v0 - __bfloat162float(h0)),
                                  __float2bfloat16(v1 - __bfloat162float(h1))};
            __nv_bfloat162 pl1 = {__float2bfloat16(v2 - __bfloat162float(h2)),
                                  __float2bfloat16(v3 - __bfloat162float(h3))};
            *(uint32_t*)(ch + (size_t)row * 768 + col) = *(uint32_t*)&ph0;
            *(uint32_t*)(ch + (size_t)(row + 8) * 768 + col) = *(uint32_t*)&ph1;
            *(uint32_t*)(cl + (size_t)row * 768 + col) = *(uint32_t*)&pl0;
            *(uint32_t*)(cl + (size_t)(row + 8) * 768 + col) = *(uint32_t*)&pl1;
        }
    }
}

// ===========================================================================
// Single-pass fp16 NT GEMM (V projection, output projection).
// Block tile 128x128, K-chunk 64, 2-stage, ONE barrier per chunk, 2 CTAs/SM.
// mode 0: write fp16 to Ch. mode 1: write fp32 + bias to Cf.
// ===========================================================================
#define FTA (128 * AST * 2)          // bytes per array per stage (18432)
#define FSTB (2 * FTA)               // stage stride (36864)

__global__ __launch_bounds__(256, 2) void gemm_f16g(
    const __half* __restrict__ Af, const __half* __restrict__ Bf,
    const float* __restrict__ bias, float* __restrict__ Cf,
    __half* __restrict__ Ch, int mode)
{
    extern __shared__ __align__(16) __half smh[];
    const uint32_t sb = smem_u32(smh);

    const int tid = threadIdx.x, wid = tid >> 5, lane = tid & 31;
    const int wm = (wid >> 1) * 32, wn = (wid & 1) * 64;
    const int m0 = blockIdx.y * 128, n0 = blockIdx.x * 128;

    const __half* gA = Af + (size_t)m0 * 768;
    const __half* gB = Bf + (size_t)n0 * 768;

    float acc[2][8][4];
#pragma unroll
    for (int i = 0; i < 2; i++)
#pragma unroll
        for (int j = 0; j < 8; j++)
#pragma unroll
            for (int k = 0; k < 4; k++) acc[i][j][k] = 0.f;

#define FSTAGE(buf, c_)                                                        \
    {                                                                          \
        uint32_t base_ = sb + (buf) * FSTB;                                    \
        const int k0_ = (c_) * 64;                                             \
        _Pragma("unroll")                                                      \
        for (int it = 0; it < 4; it++) {                                       \
            int idx = it * 256 + tid;                                          \
            int row = idx >> 3, cc = idx & 7;                                  \
            uint32_t off = (uint32_t)(row * AST + cc * 8) * 2;                 \
            size_t go = (size_t)row * 768 + k0_ + cc * 8;                      \
            cpa16(base_ + off,       gA + go);                                 \
            cpa16(base_ + FTA + off, gB + go);                                 \
        }                                                                      \
        asm volatile("cp.async.commit_group;" ::: "memory");                   \
    }

    FSTAGE(0, 0);

    const int lrow = lane & 15, lcol8 = (lane >> 4) * 8;
    const uint32_t offA = (uint32_t)((wm + lrow) * AST + lcol8) * 2;
    const uint32_t offB = (uint32_t)((wn + lrow) * AST + lcol8) * 2;

    for (int c = 0; c < 12; c++) {
        asm volatile("cp.async.wait_group 0;" ::: "memory");
        __syncthreads();
        if (c + 1 < 12) FSTAGE((c + 1) & 1, c + 1);
        uint32_t base = sb + (c & 1) * FSTB;
        uint32_t aA = base + offA, aB = base + FTA + offB;
#pragma unroll
        for (int kk = 0; kk < 4; kk++) {
            const uint32_t koff = kk * 32;
            uint32_t af[2][4];
#pragma unroll
            for (int mf = 0; mf < 2; mf++)
                ldsm_x4(af[mf], aA + mf * 16 * AST * 2 + koff);
#pragma unroll
            for (int nq = 0; nq < 4; nq++) {
                uint32_t bq[4];
                ldsm_x4(bq, aB + nq * 16 * AST * 2 + koff);
#pragma unroll
                for (int mf = 0; mf < 2; mf++) {
                    mma_f16(acc[mf][nq * 2 + 0], af[mf], bq[0], bq[2]);
                    mma_f16(acc[mf][nq * 2 + 1], af[mf], bq[1], bq[3]);
                }
            }
        }
    }

#pragma unroll
    for (int mf = 0; mf < 2; mf++) {
#pragma unroll
        for (int nf = 0; nf < 8; nf++) {
            int row = m0 + wm + mf * 16 + (lane >> 2);
            int col = n0 + wn + nf * 8 + (lane & 3) * 2;
            float v0 = acc[mf][nf][0], v1 = acc[mf][nf][1];
            float v2 = acc[mf][nf][2], v3 = acc[mf][nf][3];
            if (mode == 1) {
                float b0 = bias[col], b1 = bias[col + 1];
                *(float2*)(Cf + (size_t)row * 768 + col) = make_float2(v0 + b0, v1 + b1);
                *(float2*)(Cf + (size_t)(row + 8) * 768 + col) = make_float2(v2 + b0, v3 + b1);
            } else {
                __half2 h0 = __floats2half2_rn(v0, v1);
                __half2 h1 = __floats2half2_rn(v2, v3);
                *(uint32_t*)(Ch + (size_t)row * 768 + col) = *(uint32_t*)&h0;
                *(uint32_t*)(Ch + (size_t)(row + 8) * 768 + col) = *(uint32_t*)&h1;
            }
        }
    }
}

// ===========================================================================
// HMMA fused biased flash attention (no-max softmax, R11 design).
// Key tile 32, 3-stage cp.async pipeline (K hi/lo + V + W), 2 CTAs/SM.
// Output written directly as fp16 (feeds fp16 output projection).
// ===========================================================================
#define KT 32
#define KVB (KT * AST * 2)            // 4608 B per K/V array per stage
#define WB  (128 * WSTW * 4)          // 18432 B W tile per stage
#define STB (3 * KVB + WB)            // stage stride 32256 B

__global__ __launch_bounds__(256, 2) void attn_mma(
    const __nv_bfloat16* __restrict__ qkh, const __nv_bfloat16* __restrict__ qkl,
    const __half* __restrict__ vf, const float* __restrict__ W,
    __half* __restrict__ att16)
{
    extern __shared__ __align__(16) char smn[];
    const uint32_t sb = smem_u32(smn);

    const int tid = threadIdx.x, wp = tid >> 5, lane = tid & 31;
    const int n0 = blockIdx.x * 128, h = blockIdx.y, b = blockIdx.z;

    const __nv_bfloat16* qh = qkh + ((size_t)(b * 1024 + n0)) * 768 + h * 64;
    const __nv_bfloat16* ql = qkl + ((size_t)(b * 1024 + n0)) * 768 + h * 64;
    const __nv_bfloat16* kh = qkh + (size_t)TOTE + (size_t)b * 1024 * 768 + h * 64;
    const __nv_bfloat16* kl = qkl + (size_t)TOTE + (size_t)b * 1024 * 768 + h * 64;
    const __half* vg = vf + (size_t)b * 1024 * 768 + h * 64;
    const float* wg = W + ((size_t)(b * 12 + h) * 1024 + n0) * 1024;

    // --- Stage Q (128x64) hi/lo through smem (pre-pipeline), frags to regs ---
    {
        __nv_bfloat16* tQh = (__nv_bfloat16*)smn;
        __nv_bfloat16* tQl = tQh + 128 * AST;
#pragma unroll
        for (int it = 0; it < 4; it++) {
            int idx = it * 256 + tid;
            int row = idx >> 3, cc = idx & 7;
            *(uint4*)(tQh + row * AST + cc * 8) = *(const uint4*)(qh + (size_t)row * 768 + cc * 8);
            *(uint4*)(tQl + row * AST + cc * 8) = *(const uint4*)(ql + (size_t)row * 768 + cc * 8);
        }
    }
    __syncthreads();
    uint32_t qfh[4][4], qfl[4][4];
    {
        uint32_t off = (uint32_t)((wp * 16 + (lane & 15)) * AST + (lane >> 4) * 8) * 2;
#pragma unroll
        for (int ks = 0; ks < 4; ks++) {
            ldsm_x4(qfh[ks], sb + off + ks * 32);
            ldsm_x4(qfl[ks], sb + 128 * AST * 2 + off + ks * 32);
        }
    }
    __syncthreads();

    float oacc[8][4];
#pragma unroll
    for (int d = 0; d < 8; d++)
#pragma unroll
        for (int j = 0; j < 4; j++) oacc[d][j] = 0.f;
    float l0r = 0.f, l1r = 0.f;

#define ASTAGE(buf, t_)                                                        \
    {                                                                          \
        uint32_t base_ = sb + (buf) * STB;                                     \
        const int s0_ = (t_) * KT;                                             \
        {                                                                      \
            int row = tid >> 3, cc = tid & 7;                                  \
            uint32_t doff = (uint32_t)(row * AST + cc * 8) * 2;                \
            size_t go = (size_t)(s0_ + row) * 768 + cc * 8;                    \
            cpa16(base_ + doff,           kh + go);                            \
            cpa16(base_ + KVB + doff,     kl + go);                            \
            cpa16(base_ + 2 * KVB + doff, vg + go);                            \
        }                                                                      \
        _Pragma("unroll")                                                      \
        for (int it = 0; it < 4; it++) {                                       \
            int idx = it * 256 + tid;                                          \
            int row = idx >> 3, cc = idx & 7;                                  \
            cpa16(base_ + 3 * KVB + (uint32_t)(row * WSTW + cc * 4) * 4,       \
                  wg + (size_t)row * 1024 + s0_ + cc * 4);                     \
        }                                                                      \
        asm volatile("cp.async.commit_group;" ::: "memory");                   \
    }

    ASTAGE(0, 0); ASTAGE(1, 1);

    const uint32_t foff = (uint32_t)(((lane & 15) * AST) + (lane >> 4) * 8) * 2;
    const int c0 = (lane & 3) * 2;
    const uint32_t woff = (uint32_t)((wp * 16 + (lane >> 2)) * WSTW + c0) * 4;

    for (int t = 0; t < 32; t++) {
        if (t + 2 < 32) {
            asm volatile("cp.async.wait_group 1;" ::: "memory");
        } else {
            asm volatile("cp.async.wait_group 0;" ::: "memory");
        }
        __syncthreads();
        if (t + 2 < 32) ASTAGE((t + 2) % 3, t + 2);
        uint32_t base = sb + (t % 3) * STB;
        uint32_t kbh = base + foff, kbl = base + KVB + foff;
        uint32_t vbb = base + 2 * KVB + foff;
        uint32_t wb0 = base + 3 * KVB + woff;

        // ---- S = Q K^T (3-term split-bf16), 32 keys ----
        float sc[4][4];
#pragma unroll
        for (int nf = 0; nf < 4; nf++)
#pragma unroll
            for (int j = 0; j < 4; j++) sc[nf][j] = 0.f;
#pragma unroll
        for (int nf2 = 0; nf2 < 2; nf2++) {
#pragma unroll
            for (int ks = 0; ks < 4; ks++) {
                uint32_t off = (uint32_t)(nf2 * 16 * AST + ks * 16) * 2;
                uint32_t fh[4], fl[4];
                ldsm_x4(fh, kbh + off);
                ldsm_x4(fl, kbl + off);
                mma_bf(sc[2 * nf2],     qfh[ks], fh[0], fh[2]);
                mma_bf(sc[2 * nf2 + 1], qfh[ks], fh[1], fh[3]);
                mma_bf(sc[2 * nf2],     qfl[ks], fh[0], fh[2]);
                mma_bf(sc[2 * nf2 + 1], qfl[ks], fh[1], fh[3]);
                mma_bf(sc[2 * nf2],     qfh[ks], fl[0], fl[2]);
                mma_bf(sc[2 * nf2 + 1], qfh[ks], fl[1], fl[3]);
            }
        }

        // ---- p = exp(W + scale*S) directly (bounded logits, no max) ----
        float rs0 = 0.f, rs1 = 0.f;
#pragma unroll
        for (int nf = 0; nf < 4; nf++) {
            float2 w0, w1;
            asm volatile("ld.shared.v2.f32 {%0,%1}, [%2];"
                         : "=f"(w0.x), "=f"(w0.y) : "r"(wb0 + nf * 32));
            asm volatile("ld.shared.v2.f32 {%0,%1}, [%2];"
                         : "=f"(w1.x), "=f"(w1.y) : "r"(wb0 + 8 * WSTW * 4 + nf * 32));
            sc[nf][0] = __expf(fmaf(sc[nf][0], 0.125f, w0.x));
            sc[nf][1] = __expf(fmaf(sc[nf][1], 0.125f, w0.y));
            sc[nf][2] = __expf(fmaf(sc[nf][2], 0.125f, w1.x));
            sc[nf][3] = __expf(fmaf(sc[nf][3], 0.125f, w1.y));
            rs0 += sc[nf][0] + sc[nf][1];
            rs1 += sc[nf][2] + sc[nf][3];
        }
        l0r += rs0;
        l1r += rs1;

        // ---- out += P V (fp16, P from registers) ----
#pragma unroll
        for (int kc = 0; kc < 2; kc++) {
            uint32_t pa[4];
            pa[0] = pack_f16x2(sc[2 * kc][0], sc[2 * kc][1]);
            pa[1] = pack_f16x2(sc[2 * kc][2], sc[2 * kc][3]);
            pa[2] = pack_f16x2(sc[2 * kc + 1][0], sc[2 * kc + 1][1]);
            pa[3] = pack_f16x2(sc[2 * kc + 1][2], sc[2 * kc + 1][3]);
#pragma unroll
            for (int dp = 0; dp < 4; dp++) {
                uint32_t vf4[4];
                ldsm_x4_t(vf4, vbb + (uint32_t)(kc * 16 * AST + dp * 16) * 2);
                mma_f16(oacc[2 * dp],     pa, vf4[0], vf4[1]);
                mma_f16(oacc[2 * dp + 1], pa, vf4[2], vf4[3]);
            }
        }
    }

    // ---- normalize + write fp16 (att layout [4096, 768]) ----
    l0r += __shfl_xor_sync(0xffffffffu, l0r, 1);
    l0r += __shfl_xor_sync(0xffffffffu, l0r, 2);
    l1r += __shfl_xor_sync(0xffffffffu, l1r, 1);
    l1r += __shfl_xor_sync(0xffffffffu, l1r, 2);
    float i0 = 1.f / l0r, i1 = 1.f / l1r;
    int row = b * 1024 + n0 + wp * 16 + (lane >> 2);
    int colb = h * 64 + c0;
#pragma unroll
    for (int d = 0; d < 8; d++) {
        __half2 h0 = __floats2half2_rn(oacc[d][0] * i0, oacc[d][1] * i0);
        __half2 h1 = __floats2half2_rn(oacc[d][2] * i1, oacc[d][3] * i1);
        *(uint32_t*)(att16 + (size_t)row * 768 + colb + d * 8) = *(uint32_t*)&h0;
        *(uint32_t*)(att16 + (size_t)(row + 8) * 768 + colb + d * 8) = *(uint32_t*)&h1;
    }
}

// ===========================================================================
// Launch
// ===========================================================================
extern "C" void kernel_launch(void* const* d_in, const int* in_sizes, int n_in,
                              void* d_out, int out_size)
{
    const float* query = (const float*)d_in[0];
    const float* attw  = (const float*)d_in[1];
    const float* Wq    = (const float*)d_in[2];
    const float* Wk    = (const float*)d_in[3];
    const float* Wv    = (const float*)d_in[4];
    const float* Wo    = (const float*)d_in[5];
    const float* bo    = (const float*)d_in[6];
    float* out = (float*)d_out;

    __nv_bfloat16 *ahi, *alo, *whi, *wlo, *qkh, *qkl;
    __half *qf16, *wf16, *vfp, *att16;
    cudaGetSymbolAddress((void**)&ahi, g_ahi);
    cudaGetSymbolAddress((void**)&alo, g_alo);
    cudaGetSymbolAddress((void**)&qf16, g_qf16);
    cudaGetSymbolAddress((void**)&whi, g_whi);
    cudaGetSymbolAddress((void**)&wlo, g_wlo);
    cudaGetSymbolAddress((void**)&wf16, g_wf16);
    cudaGetSymbolAddress((void**)&qkh, g_qkh);
    cudaGetSymbolAddress((void**)&qkl, g_qkl);
    cudaGetSymbolAddress((void**)&vfp, g_vf);
    cudaGetSymbolAddress((void**)&att16, g_att16);

    const int bf3_smem = 2 * GSTB;                 // 110592 (2 CTAs/SM)
    cudaFuncSetAttribute(gemm_bf3, cudaFuncAttributeMaxDynamicSharedMemorySize, bf3_smem);
    const int f16_smem = 2 * FSTB;                 // 73728 (2 CTAs/SM)
    cudaFuncSetAttribute(gemm_f16g, cudaFuncAttributeMaxDynamicSharedMemorySize, f16_smem);
    const int attn_smem = 3 * STB;                 // 96768 (2 CTAs/SM)
    cudaFuncSetAttribute(attn_mma, cudaFuncAttributeMaxDynamicSharedMemorySize, attn_smem);

    // 1) Conversions: query -> hi/lo + fp16; Wq/Wk -> hi/lo; Wv/Wo -> fp16
    split_q<<<TOTE / 4 / 256, 256>>>((const float4*)query, (uint2*)ahi, (uint2*)alo,
                                     (uint2*)qf16, TOTE / 4);
    split_w<<<dim3(WELE / 4 / 256, 2), 256>>>((const float4*)Wq, (const float4*)Wk,
                                              (uint2*)whi, (uint2*)wlo);
    conv_w16<<<dim3(WELE / 4 / 256, 2), 256>>>((const float4*)Wv, (const float4*)Wo,
                                               (uint2*)wf16);

    // 2) Q,K projections (3-term bf16) -> bf16 hi/lo
    gemm_bf3<<<dim3(12, 32, 2), 256, bf3_smem>>>(ahi, alo, whi, wlo, qkh, qkl);

    // 3) V projection (single-pass fp16) -> fp16
    gemm_f16g<<<dim3(6, 32), 256, f16_smem>>>(qf16, wf16, nullptr, nullptr, vfp, 0);

    // 4) Fused biased attention -> att fp16
    attn_mma<<<dim3(8, 12, 4), 256, attn_smem>>>(qkh, qkl, vfp, attw, att16);

    // 5) Output projection (single-pass fp16) -> fp32 + bias
    gemm_f16g<<<dim3(6, 32), 256, f16_smem>>>(att16, wf16 + WELE, bo, out, nullptr, 1);
}

// round 13
// speedup vs baseline: 1.2647x; 1.0873x over previous
#include <cuda_runtime.h>
#include <cuda_bf16.h>
#include <cuda_fp16.h>
#include <math.h>
#include <cstdint>

#define TOTE (4096 * 768)
#define WELE (768 * 768)
#define AST 72     // bf16/fp16 smem row stride for 64-wide tiles (144B)
#define WSTW 36    // W fp32 smem row stride (144B)

// Scratch (allocation-free rule: __device__ globals)
__device__ __nv_bfloat16 g_ahi[TOTE];        // query hi
__device__ __nv_bfloat16 g_alo[TOTE];        // query lo
__device__ __half        g_qf16[TOTE];       // query fp16 (for V projection)
__device__ __nv_bfloat16 g_whi[2 * WELE];    // Wq|Wk hi
__device__ __nv_bfloat16 g_wlo[2 * WELE];    // Wq|Wk lo
__device__ __half        g_wf16[2 * WELE];   // Wv|Wo fp16
__device__ __nv_bfloat16 g_qkh[2 * TOTE];    // Q|K hi
__device__ __nv_bfloat16 g_qkl[2 * TOTE];    // Q|K lo
__device__ __half        g_vf[TOTE];         // V fp16
__device__ __half        g_att16[TOTE];      // attention output fp16

// ===========================================================================
// Base-sm_103-safe helpers (no tcgen05: ptxas virtual target is compute_103)
// ===========================================================================
__device__ __forceinline__ uint32_t smem_u32(const void* p) {
    uint32_t a;
    asm("{ .reg .u64 t; cvta.to.shared.u64 t, %1; cvt.u32.u64 %0, t; }" : "=r"(a) : "l"(p));
    return a;
}
__device__ __forceinline__ void ldsm_x4(uint32_t* r, uint32_t addr) {
    asm volatile("ldmatrix.sync.aligned.m8n8.x4.shared.b16 {%0,%1,%2,%3}, [%4];"
                 : "=r"(r[0]), "=r"(r[1]), "=r"(r[2]), "=r"(r[3]) : "r"(addr));
}
__device__ __forceinline__ void ldsm_x4_t(uint32_t* r, uint32_t addr) {
    asm volatile("ldmatrix.sync.aligned.m8n8.x4.trans.shared.b16 {%0,%1,%2,%3}, [%4];"
                 : "=r"(r[0]), "=r"(r[1]), "=r"(r[2]), "=r"(r[3]) : "r"(addr));
}
__device__ __forceinline__ void mma_bf(float* d, const uint32_t* a, uint32_t b0, uint32_t b1) {
    asm volatile(
        "mma.sync.aligned.m16n8k16.row.col.f32.bf16.bf16.f32 "
        "{%0,%1,%2,%3}, {%4,%5,%6,%7}, {%8,%9}, {%0,%1,%2,%3};"
        : "+f"(d[0]), "+f"(d[1]), "+f"(d[2]), "+f"(d[3])
        : "r"(a[0]), "r"(a[1]), "r"(a[2]), "r"(a[3]), "r"(b0), "r"(b1));
}
__device__ __forceinline__ void mma_f16(float* d, const uint32_t* a, uint32_t b0, uint32_t b1) {
    asm volatile(
        "mma.sync.aligned.m16n8k16.row.col.f32.f16.f16.f32 "
        "{%0,%1,%2,%3}, {%4,%5,%6,%7}, {%8,%9}, {%0,%1,%2,%3};"
        : "+f"(d[0]), "+f"(d[1]), "+f"(d[2]), "+f"(d[3])
        : "r"(a[0]), "r"(a[1]), "r"(a[2]), "r"(a[3]), "r"(b0), "r"(b1));
}
__device__ __forceinline__ uint32_t pack_f16x2(float lo, float hi) {
    uint32_t d;
    asm("cvt.rn.f16x2.f32 %0, %1, %2;" : "=r"(d) : "f"(hi), "f"(lo));
    return d;
}
__device__ __forceinline__ void cpa16(uint32_t dst, const void* src) {
    asm volatile("cp.async.cg.shared.global [%0], [%1], 16;" :: "r"(dst), "l"(src) : "memory");
}

// ===========================================================================
// Fused conversion kernel (one launch).
// bid ranges: [0,3072) query->hi/lo+fp16 | [3072,4224) Wq/Wk->hi/lo |
//             [4224,5376) Wv/Wo->fp16
// ===========================================================================
__global__ __launch_bounds__(256) void conv_all(
    const float4* __restrict__ q,
    const float4* __restrict__ Wq, const float4* __restrict__ Wk,
    const float4* __restrict__ Wv, const float4* __restrict__ Wo,
    uint2* __restrict__ ahi, uint2* __restrict__ alo, uint2* __restrict__ qf16,
    uint2* __restrict__ whi, uint2* __restrict__ wlo, uint2* __restrict__ wf16)
{
    const int bid = blockIdx.x;
    const int tid = threadIdx.x;
    if (bid < 3072) {
        int i = bid * 256 + tid;                   // < TOTE/4
        float4 v = q[i];
        float vv[4] = {v.x, v.y, v.z, v.w};
        __nv_bfloat16 h[4], l[4];
        __half f[4];
#pragma unroll
        for (int j = 0; j < 4; j++) {
            h[j] = __float2bfloat16(vv[j]);
            l[j] = __float2bfloat16(vv[j] - __bfloat162float(h[j]));
            f[j] = __float2half_rn(vv[j]);
        }
        ahi[i] = *(uint2*)h;
        alo[i] = *(uint2*)l;
        qf16[i] = *(uint2*)f;
    } else if (bid < 4224) {
        int r = bid - 3072;
        int zz = r / 576;
        int i = (r % 576) * 256 + tid;             // < WELE/4
        const float4* src = zz ? Wk : Wq;
        float4 v = src[i];
        float vv[4] = {v.x, v.y, v.z, v.w};
        __nv_bfloat16 h[4], l[4];
#pragma unroll
        for (int j = 0; j < 4; j++) {
            h[j] = __float2bfloat16(vv[j]);
            l[j] = __float2bfloat16(vv[j] - __bfloat162float(h[j]));
        }
        whi[(size_t)zz * (WELE / 4) + i] = *(uint2*)h;
        wlo[(size_t)zz * (WELE / 4) + i] = *(uint2*)l;
    } else {
        int r = bid - 4224;
        int zz = r / 576;
        int i = (r % 576) * 256 + tid;
        const float4* src = zz ? Wo : Wv;
        float4 v = src[i];
        __half f[4] = {__float2half_rn(v.x), __float2half_rn(v.y),
                       __float2half_rn(v.z), __float2half_rn(v.w)};
        wf16[(size_t)zz * (WELE / 4) + i] = *(uint2*)f;
    }
}

// ===========================================================================
// Fused projection kernel: one launch computes Q, K (3-term split-bf16,
// tile 128x64) AND V (single-pass fp16, tile 128x128).
// z in {0,1}: bf3 path. z==2: fp16 V path (uses x<6 only; others exit and
// free their SM slot — packs V work into the QK grid's partial last wave).
// 2-stage cp.async, ONE barrier per chunk, 2 CTAs/SM.
// ===========================================================================
#define GTA (128 * AST * 2)          // A array bytes/stage (18432)
#define GTB (64 * AST * 2)           // B array bytes/stage (9216)
#define GSTB (2 * GTA + 2 * GTB)     // bf3 stage stride (55296)
#define FTA (128 * AST * 2)          // f16 array bytes/stage (18432)
#define FSTB (2 * FTA)               // f16 stage stride (36864)

__global__ __launch_bounds__(256, 2) void proj_all(
    const __nv_bfloat16* __restrict__ Ahi, const __nv_bfloat16* __restrict__ Alo,
    const __nv_bfloat16* __restrict__ Whi, const __nv_bfloat16* __restrict__ Wlo,
    const __half* __restrict__ Af, const __half* __restrict__ Bf,
    __nv_bfloat16* __restrict__ Chi, __nv_bfloat16* __restrict__ Clo,
    __half* __restrict__ Ch)
{
    extern __shared__ __align__(16) char smraw[];
    const uint32_t sb = smem_u32(smraw);
    const int tid = threadIdx.x, wid = tid >> 5, lane = tid & 31;
    const int z = blockIdx.z;

    if (z == 2) {
        // ---------------- V projection: single-pass fp16, 128x128 ----------
        if (blockIdx.x >= 6) return;
        const int wm = (wid >> 1) * 32, wn = (wid & 1) * 64;
        const int m0 = blockIdx.y * 128, n0 = blockIdx.x * 128;
        const __half* gA = Af + (size_t)m0 * 768;
        const __half* gB = Bf + (size_t)n0 * 768;

        float acc[2][8][4];
#pragma unroll
        for (int i = 0; i < 2; i++)
#pragma unroll
            for (int j = 0; j < 8; j++)
#pragma unroll
                for (int k = 0; k < 4; k++) acc[i][j][k] = 0.f;

#define FSTAGE(buf, c_)                                                        \
    {                                                                          \
        uint32_t base_ = sb + (buf) * FSTB;                                    \
        const int k0_ = (c_) * 64;                                             \
        _Pragma("unroll")                                                      \
        for (int it = 0; it < 4; it++) {                                       \
            int idx = it * 256 + tid;                                          \
            int row = idx >> 3, cc = idx & 7;                                  \
            uint32_t off = (uint32_t)(row * AST + cc * 8) * 2;                 \
            size_t go = (size_t)row * 768 + k0_ + cc * 8;                      \
            cpa16(base_ + off,       gA + go);                                 \
            cpa16(base_ + FTA + off, gB + go);                                 \
        }                                                                      \
        asm volatile("cp.async.commit_group;" ::: "memory");                   \
    }

        FSTAGE(0, 0);
        const int lrow = lane & 15, lcol8 = (lane >> 4) * 8;
        const uint32_t offA = (uint32_t)((wm + lrow) * AST + lcol8) * 2;
        const uint32_t offB = (uint32_t)((wn + lrow) * AST + lcol8) * 2;

        for (int c = 0; c < 12; c++) {
            asm volatile("cp.async.wait_group 0;" ::: "memory");
            __syncthreads();
            if (c + 1 < 12) FSTAGE((c + 1) & 1, c + 1);
            uint32_t base = sb + (c & 1) * FSTB;
            uint32_t aA = base + offA, aB = base + FTA + offB;
#pragma unroll
            for (int kk = 0; kk < 4; kk++) {
                const uint32_t koff = kk * 32;
                uint32_t af[2][4];
#pragma unroll
                for (int mf = 0; mf < 2; mf++)
                    ldsm_x4(af[mf], aA + mf * 16 * AST * 2 + koff);
#pragma unroll
                for (int nq = 0; nq < 4; nq++) {
                    uint32_t bq[4];
                    ldsm_x4(bq, aB + nq * 16 * AST * 2 + koff);
#pragma unroll
                    for (int mf = 0; mf < 2; mf++) {
                        mma_f16(acc[mf][nq * 2 + 0], af[mf], bq[0], bq[2]);
                        mma_f16(acc[mf][nq * 2 + 1], af[mf], bq[1], bq[3]);
                    }
                }
            }
        }

#pragma unroll
        for (int mf = 0; mf < 2; mf++) {
#pragma unroll
            for (int nf = 0; nf < 8; nf++) {
                int row = m0 + wm + mf * 16 + (lane >> 2);
                int col = n0 + wn + nf * 8 + (lane & 3) * 2;
                __half2 h0 = __floats2half2_rn(acc[mf][nf][0], acc[mf][nf][1]);
                __half2 h1 = __floats2half2_rn(acc[mf][nf][2], acc[mf][nf][3]);
                *(uint32_t*)(Ch + (size_t)row * 768 + col) = *(uint32_t*)&h0;
                *(uint32_t*)(Ch + (size_t)(row + 8) * 768 + col) = *(uint32_t*)&h1;
            }
        }
        return;
    }

    // ---------------- Q,K projections: 3-term split-bf16, 128x64 ----------
    const int wm = (wid >> 1) * 32, wn = (wid & 1) * 32;
    const int m0 = blockIdx.y * 128, n0 = blockIdx.x * 64;

    const __nv_bfloat16* gAh = Ahi + (size_t)m0 * 768;
    const __nv_bfloat16* gAl = Alo + (size_t)m0 * 768;
    const __nv_bfloat16* gBh = Whi + (size_t)z * WELE + (size_t)n0 * 768;
    const __nv_bfloat16* gBl = Wlo + (size_t)z * WELE + (size_t)n0 * 768;

    float acc[2][4][4];
#pragma unroll
    for (int i = 0; i < 2; i++)
#pragma unroll
        for (int j = 0; j < 4; j++)
#pragma unroll
            for (int k = 0; k < 4; k++) acc[i][j][k] = 0.f;

#define GSTAGE(buf, c_)                                                        \
    {                                                                          \
        uint32_t base_ = sb + (buf) * GSTB;                                    \
        const int k0_ = (c_) * 64;                                             \
        _Pragma("unroll")                                                      \
        for (int it = 0; it < 4; it++) {                                       \
            int idx = it * 256 + tid;                                          \
            int row = idx >> 3, cc = idx & 7;                                  \
            uint32_t off = (uint32_t)(row * AST + cc * 8) * 2;                 \
            size_t go = (size_t)row * 768 + k0_ + cc * 8;                      \
            cpa16(base_ + off,       gAh + go);                                \
            cpa16(base_ + GTA + off, gAl + go);                                \
        }                                                                      \
        _Pragma("unroll")                                                      \
        for (int it = 0; it < 2; it++) {                                       \
            int idx = it * 256 + tid;                                          \
            int row = idx >> 3, cc = idx & 7;                                  \
            uint32_t off = (uint32_t)(row * AST + cc * 8) * 2;                 \
            size_t go = (size_t)row * 768 + k0_ + cc * 8;                      \
            cpa16(base_ + 2 * GTA + off,       gBh + go);                      \
            cpa16(base_ + 2 * GTA + GTB + off, gBl + go);                      \
        }                                                                      \
        asm volatile("cp.async.commit_group;" ::: "memory");                   \
    }

    GSTAGE(0, 0);

    const int lrow = lane & 15, lcol8 = (lane >> 4) * 8;
    const uint32_t offA = (uint32_t)((wm + lrow) * AST + lcol8) * 2;
    const uint32_t offB = (uint32_t)((wn + lrow) * AST + lcol8) * 2;

    for (int c = 0; c < 12; c++) {
        asm volatile("cp.async.wait_group 0;" ::: "memory");
        __syncthreads();
        if (c + 1 < 12) GSTAGE((c + 1) & 1, c + 1);
        uint32_t base = sb + (c & 1) * GSTB;
        uint32_t aAh = base + offA, aAl = base + GTA + offA;
        uint32_t aBh = base + 2 * GTA + offB, aBl = base + 2 * GTA + GTB + offB;
#pragma unroll
        for (int kk = 0; kk < 4; kk++) {
            const uint32_t koff = kk * 32;
            uint32_t ah[2][4], al[2][4], bh[2][4], bl[2][4];
#pragma unroll
            for (int mf = 0; mf < 2; mf++) {
                ldsm_x4(ah[mf], aAh + mf * 16 * AST * 2 + koff);
                ldsm_x4(al[mf], aAl + mf * 16 * AST * 2 + koff);
            }
#pragma unroll
            for (int nq = 0; nq < 2; nq++) {
                ldsm_x4(bh[nq], aBh + nq * 16 * AST * 2 + koff);
                ldsm_x4(bl[nq], aBl + nq * 16 * AST * 2 + koff);
            }
#pragma unroll
            for (int mf = 0; mf < 2; mf++) {
#pragma unroll
                for (int nq = 0; nq < 2; nq++) {
                    float* a0 = acc[mf][nq * 2 + 0];
                    float* a1 = acc[mf][nq * 2 + 1];
                    mma_bf(a0, ah[mf], bh[nq][0], bh[nq][2]);
                    mma_bf(a1, ah[mf], bh[nq][1], bh[nq][3]);
                    mma_bf(a0, al[mf], bh[nq][0], bh[nq][2]);
                    mma_bf(a1, al[mf], bh[nq][1], bh[nq][3]);
                    mma_bf(a0, ah[mf], bl[nq][0], bl[nq][2]);
                    mma_bf(a1, ah[mf], bl[nq][1], bl[nq][3]);
                }
            }
        }
    }

#pragma unroll
    for (int mf = 0; mf < 2; mf++) {
#pragma unroll
        for (int nf = 0; nf < 4; nf++) {
            int row = m0 + wm + mf * 16 + (lane >> 2);
            int col = n0 + wn + nf * 8 + (lane & 3) * 2;
            float v0 = acc[mf][nf][0], v1 = acc[mf][nf][1];
            float v2 = acc[mf][nf][2], v3 = acc[mf][nf][3];
            __nv_bfloat16* ch = Chi + (size_t)z * TOTE;
            __nv_bfloat16* cl = Clo + (size_t)z * TOTE;
            __nv_bfloat16 h0 = __float2bfloat16(v0), h1 = __float2bfloat16(v1);
            __nv_bfloat16 h2 = __float2bfloat16(v2), h3 = __float2bfloat16(v3);
            __nv_bfloat162 ph0 = {h0, h1}, ph1 = {h2, h3};
            __nv_bfloat162 pl0 = {__float2bfloat16(v0 - __bfloat162float(h0)),
                                  __float2bfloat16(v1 - __bfloat162float(h1))};
            __nv_bfloat162 pl1 = {__float2bfloat16(v2 - __bfloat162float(h2)),
                                  __float2bfloat16(v3 - __bfloat162float(h3))};
            *(uint32_t*)(ch + (size_t)row * 768 + col) = *(uint32_t*)&ph0;
            *(uint32_t*)(ch + (size_t)(row + 8) * 768 + col) = *(uint32_t*)&ph1;
            *(uint32_t*)(cl + (size_t)row * 768 + col) = *(uint32_t*)&pl0;
            *(uint32_t*)(cl + (size_t)(row + 8) * 768 + col) = *(uint32_t*)&pl1;
        }
    }
}

// ===========================================================================
// Output projection: single-pass fp16 NT GEMM, fp32 + bias epilogue.
// Block tile 128x128, K-chunk 64, 2-stage, ONE barrier per chunk, 2 CTAs/SM.
// ===========================================================================
__global__ __launch_bounds__(256, 2) void gemm_out(
    const __half* __restrict__ Af, const __half* __restrict__ Bf,
    const float* __restrict__ bias, float* __restrict__ Cf)
{
    extern __shared__ __align__(16) __half smh[];
    const uint32_t sb = smem_u32(smh);

    const int tid = threadIdx.x, wid = tid >> 5, lane = tid & 31;
    const int wm = (wid >> 1) * 32, wn = (wid & 1) * 64;
    const int m0 = blockIdx.y * 128, n0 = blockIdx.x * 128;

    const __half* gA = Af + (size_t)m0 * 768;
    const __half* gB = Bf + (size_t)n0 * 768;

    float acc[2][8][4];
#pragma unroll
    for (int i = 0; i < 2; i++)
#pragma unroll
        for (int j = 0; j < 8; j++)
#pragma unroll
            for (int k = 0; k < 4; k++) acc[i][j][k] = 0.f;

#define OSTAGE(buf, c_)                                                        \
    {                                                                          \
        uint32_t base_ = sb + (buf) * FSTB;                                    \
        const int k0_ = (c_) * 64;                                             \
        _Pragma("unroll")                                                      \
        for (int it = 0; it < 4; it++) {                                       \
            int idx = it * 256 + tid;                                          \
            int row = idx >> 3, cc = idx & 7;                                  \
            uint32_t off = (uint32_t)(row * AST + cc * 8) * 2;                 \
            size_t go = (size_t)row * 768 + k0_ + cc * 8;                      \
            cpa16(base_ + off,       gA + go);                                 \
            cpa16(base_ + FTA + off, gB + go);                                 \
        }                                                                      \
        asm volatile("cp.async.commit_group;" ::: "memory");                   \
    }

    OSTAGE(0, 0);

    const int lrow = lane & 15, lcol8 = (lane >> 4) * 8;
    const uint32_t offA = (uint32_t)((wm + lrow) * AST + lcol8) * 2;
    const uint32_t offB = (uint32_t)((wn + lrow) * AST + lcol8) * 2;

    for (int c = 0; c < 12; c++) {
        asm volatile("cp.async.wait_group 0;" ::: "memory");
        __syncthreads();
        if (c + 1 < 12) OSTAGE((c + 1) & 1, c + 1);
        uint32_t base = sb + (c & 1) * FSTB;
        uint32_t aA = base + offA, aB = base + FTA + offB;
#pragma unroll
        for (int kk = 0; kk < 4; kk++) {
            const uint32_t koff = kk * 32;
            uint32_t af[2][4];
#pragma unroll
            for (int mf = 0; mf < 2; mf++)
                ldsm_x4(af[mf], aA + mf * 16 * AST * 2 + koff);
#pragma unroll
            for (int nq = 0; nq < 4; nq++) {
                uint32_t bq[4];
                ldsm_x4(bq, aB + nq * 16 * AST * 2 + koff);
#pragma unroll
                for (int mf = 0; mf < 2; mf++) {
                    mma_f16(acc[mf][nq * 2 + 0], af[mf], bq[0], bq[2]);
                    mma_f16(acc[mf][nq * 2 + 1], af[mf], bq[1], bq[3]);
                }
            }
        }
    }

#pragma unroll
    for (int mf = 0; mf < 2; mf++) {
#pragma unroll
        for (int nf = 0; nf < 8; nf++) {
            int row = m0 + wm + mf * 16 + (lane >> 2);
            int col = n0 + wn + nf * 8 + (lane & 3) * 2;
            float b0 = bias[col], b1 = bias[col + 1];
            *(float2*)(Cf + (size_t)row * 768 + col) =
                make_float2(acc[mf][nf][0] + b0, acc[mf][nf][1] + b1);
            *(float2*)(Cf + (size_t)(row + 8) * 768 + col) =
                make_float2(acc[mf][nf][2] + b0, acc[mf][nf][3] + b1);
        }
    }
}

// ===========================================================================
// HMMA fused biased flash attention (no-max softmax).
// Key tile 32, 3-stage cp.async pipeline (K hi/lo + V + W), 2 CTAs/SM.
// ===========================================================================
#define KT 32
#define KVB (KT * AST * 2)            // 4608 B per K/V array per stage
#define WB  (128 * WSTW * 4)          // 18432 B W tile per stage
#define STB (3 * KVB + WB)            // stage stride 32256 B

__global__ __launch_bounds__(256, 2) void attn_mma(
    const __nv_bfloat16* __restrict__ qkh, const __nv_bfloat16* __restrict__ qkl,
    const __half* __restrict__ vf, const float* __restrict__ W,
    __half* __restrict__ att16)
{
    extern __shared__ __align__(16) char smn[];
    const uint32_t sb = smem_u32(smn);

    const int tid = threadIdx.x, wp = tid >> 5, lane = tid & 31;
    const int n0 = blockIdx.x * 128, h = blockIdx.y, b = blockIdx.z;

    const __nv_bfloat16* qh = qkh + ((size_t)(b * 1024 + n0)) * 768 + h * 64;
    const __nv_bfloat16* ql = qkl + ((size_t)(b * 1024 + n0)) * 768 + h * 64;
    const __nv_bfloat16* kh = qkh + (size_t)TOTE + (size_t)b * 1024 * 768 + h * 64;
    const __nv_bfloat16* kl = qkl + (size_t)TOTE + (size_t)b * 1024 * 768 + h * 64;
    const __half* vg = vf + (size_t)b * 1024 * 768 + h * 64;
    const float* wg = W + ((size_t)(b * 12 + h) * 1024 + n0) * 1024;

    // --- Stage Q (128x64) hi/lo through smem (pre-pipeline), frags to regs ---
    {
        __nv_bfloat16* tQh = (__nv_bfloat16*)smn;
        __nv_bfloat16* tQl = tQh + 128 * AST;
#pragma unroll
        for (int it = 0; it < 4; it++) {
            int idx = it * 256 + tid;
            int row = idx >> 3, cc = idx & 7;
            *(uint4*)(tQh + row * AST + cc * 8) = *(const uint4*)(qh + (size_t)row * 768 + cc * 8);
            *(uint4*)(tQl + row * AST + cc * 8) = *(const uint4*)(ql + (size_t)row * 768 + cc * 8);
        }
    }
    __syncthreads();
    uint32_t qfh[4][4], qfl[4][4];
    {
        uint32_t off = (uint32_t)((wp * 16 + (lane & 15)) * AST + (lane >> 4) * 8) * 2;
#pragma unroll
        for (int ks = 0; ks < 4; ks++) {
            ldsm_x4(qfh[ks], sb + off + ks * 32);
            ldsm_x4(qfl[ks], sb + 128 * AST * 2 + off + ks * 32);
        }
    }
    __syncthreads();

    float oacc[8][4];
#pragma unroll
    for (int d = 0; d < 8; d++)
#pragma unroll
        for (int j = 0; j < 4; j++) oacc[d][j] = 0.f;
    float l0r = 0.f, l1r = 0.f;

#define ASTAGE(buf, t_)                                                        \
    {                                                                          \
        uint32_t base_ = sb + (buf) * STB;                                     \
        const int s0_ = (t_) * KT;                                             \
        {                                                                      \
            int row = tid >> 3, cc = tid & 7;                                  \
            uint32_t doff = (uint32_t)(row * AST + cc * 8) * 2;                \
            size_t go = (size_t)(s0_ + row) * 768 + cc * 8;                    \
            cpa16(base_ + doff,           kh + go);                            \
            cpa16(base_ + KVB + doff,     kl + go);                            \
            cpa16(base_ + 2 * KVB + doff, vg + go);                            \
        }                                                                      \
        _Pragma("unroll")                                                      \
        for (int it = 0; it < 4; it++) {                                       \
            int idx = it * 256 + tid;                                          \
            int row = idx >> 3, cc = idx & 7;                                  \
            cpa16(base_ + 3 * KVB + (uint32_t)(row * WSTW + cc * 4) * 4,       \
                  wg + (size_t)row * 1024 + s0_ + cc * 4);                     \
        }                                                                      \
        asm volatile("cp.async.commit_group;" ::: "memory");                   \
    }

    ASTAGE(0, 0); ASTAGE(1, 1);

    const uint32_t foff = (uint32_t)(((lane & 15) * AST) + (lane >> 4) * 8) * 2;
    const int c0 = (lane & 3) * 2;
    const uint32_t woff = (uint32_t)((wp * 16 + (lane >> 2)) * WSTW + c0) * 4;

    for (int t = 0; t < 32; t++) {
        if (t + 2 < 32) {
            asm volatile("cp.async.wait_group 1;" ::: "memory");
        } else {
            asm volatile("cp.async.wait_group 0;" ::: "memory");
        }
        __syncthreads();
        if (t + 2 < 32) ASTAGE((t + 2) % 3, t + 2);
        uint32_t base = sb + (t % 3) * STB;
        uint32_t kbh = base + foff, kbl = base + KVB + foff;
        uint32_t vbb = base + 2 * KVB + foff;
        uint32_t wb0 = base + 3 * KVB + woff;

        // ---- S = Q K^T (3-term split-bf16), 32 keys ----
        float sc[4][4];
#pragma unroll
        for (int nf = 0; nf < 4; nf++)
#pragma unroll
            for (int j = 0; j < 4; j++) sc[nf][j] = 0.f;
#pragma unroll
        for (int nf2 = 0; nf2 < 2; nf2++) {
#pragma unroll
            for (int ks = 0; ks < 4; ks++) {
                uint32_t off = (uint32_t)(nf2 * 16 * AST + ks * 16) * 2;
                uint32_t fh[4], fl[4];
                ldsm_x4(fh, kbh + off);
                ldsm_x4(fl, kbl + off);
                mma_bf(sc[2 * nf2],     qfh[ks], fh[0], fh[2]);
                mma_bf(sc[2 * nf2 + 1], qfh[ks], fh[1], fh[3]);
                mma_bf(sc[2 * nf2],     qfl[ks], fh[0], fh[2]);
                mma_bf(sc[2 * nf2 + 1], qfl[ks], fh[1], fh[3]);
                mma_bf(sc[2 * nf2],     qfh[ks], fl[0], fl[2]);
                mma_bf(sc[2 * nf2 + 1], qfh[ks], fl[1], fl[3]);
            }
        }

        // ---- p = exp(W + scale*S) directly (bounded logits, no max) ----
        float rs0 = 0.f, rs1 = 0.f;
#pragma unroll
        for (int nf = 0; nf < 4; nf++) {
            float2 w0, w1;
            asm volatile("ld.shared.v2.f32 {%0,%1}, [%2];"
                         : "=f"(w0.x), "=f"(w0.y) : "r"(wb0 + nf * 32));
            asm volatile("ld.shared.v2.f32 {%0,%1}, [%2];"
                         : "=f"(w1.x), "=f"(w1.y) : "r"(wb0 + 8 * WSTW * 4 + nf * 32));
            sc[nf][0] = __expf(fmaf(sc[nf][0], 0.125f, w0.x));
            sc[nf][1] = __expf(fmaf(sc[nf][1], 0.125f, w0.y));
            sc[nf][2] = __expf(fmaf(sc[nf][2], 0.125f, w1.x));
            sc[nf][3] = __expf(fmaf(sc[nf][3], 0.125f, w1.y));
            rs0 += sc[nf][0] + sc[nf][1];
            rs1 += sc[nf][2] + sc[nf][3];
        }
        l0r += rs0;
        l1r += rs1;

        // ---- out += P V (fp16, P from registers) ----
#pragma unroll
        for (int kc = 0; kc < 2; kc++) {
            uint32_t pa[4];
            pa[0] = pack_f16x2(sc[2 * kc][0], sc[2 * kc][1]);
            pa[1] = pack_f16x2(sc[2 * kc][2], sc[2 * kc][3]);
            pa[2] = pack_f16x2(sc[2 * kc + 1][0], sc[2 * kc + 1][1]);
            pa[3] = pack_f16x2(sc[2 * kc + 1][2], sc[2 * kc + 1][3]);
#pragma unroll
            for (int dp = 0; dp < 4; dp++) {
                uint32_t vf4[4];
                ldsm_x4_t(vf4, vbb + (uint32_t)(kc * 16 * AST + dp * 16) * 2);
                mma_f16(oacc[2 * dp],     pa, vf4[0], vf4[1]);
                mma_f16(oacc[2 * dp + 1], pa, vf4[2], vf4[3]);
            }
        }
    }

    // ---- normalize + write fp16 (att layout [4096, 768]) ----
    l0r += __shfl_xor_sync(0xffffffffu, l0r, 1);
    l0r += __shfl_xor_sync(0xffffffffu, l0r, 2);
    l1r += __shfl_xor_sync(0xffffffffu, l1r, 1);
    l1r += __shfl_xor_sync(0xffffffffu, l1r, 2);
    float i0 = 1.f / l0r, i1 = 1.f / l1r;
    int row = b * 1024 + n0 + wp * 16 + (lane >> 2);
    int colb = h * 64 + c0;
#pragma unroll
    for (int d = 0; d < 8; d++) {
        __half2 h0 = __floats2half2_rn(oacc[d][0] * i0, oacc[d][1] * i0);
        __half2 h1 = __floats2half2_rn(oacc[d][2] * i1, oacc[d][3] * i1);
        *(uint32_t*)(att16 + (size_t)row * 768 + colb + d * 8) = *(uint32_t*)&h0;
        *(uint32_t*)(att16 + (size_t)(row + 8) * 768 + colb + d * 8) = *(uint32_t*)&h1;
    }
}

// ===========================================================================
// Launch
// ===========================================================================
extern "C" void kernel_launch(void* const* d_in, const int* in_sizes, int n_in,
                              void* d_out, int out_size)
{
    const float* query = (const float*)d_in[0];
    const float* attw  = (const float*)d_in[1];
    const float* Wq    = (const float*)d_in[2];
    const float* Wk    = (const float*)d_in[3];
    const float* Wv    = (const float*)d_in[4];
    const float* Wo    = (const float*)d_in[5];
    const float* bo    = (const float*)d_in[6];
    float* out = (float*)d_out;

    __nv_bfloat16 *ahi, *alo, *whi, *wlo, *qkh, *qkl;
    __half *qf16, *wf16, *vfp, *att16;
    cudaGetSymbolAddress((void**)&ahi, g_ahi);
    cudaGetSymbolAddress((void**)&alo, g_alo);
    cudaGetSymbolAddress((void**)&qf16, g_qf16);
    cudaGetSymbolAddress((void**)&whi, g_whi);
    cudaGetSymbolAddress((void**)&wlo, g_wlo);
    cudaGetSymbolAddress((void**)&wf16, g_wf16);
    cudaGetSymbolAddress((void**)&qkh, g_qkh);
    cudaGetSymbolAddress((void**)&qkl, g_qkl);
    cudaGetSymbolAddress((void**)&vfp, g_vf);
    cudaGetSymbolAddress((void**)&att16, g_att16);

    const int proj_smem = 2 * GSTB;                // 110592 (2 CTAs/SM; >= f16 path's 73728)
    cudaFuncSetAttribute(proj_all, cudaFuncAttributeMaxDynamicSharedMemorySize, proj_smem);
    const int out_smem = 2 * FSTB;                 // 73728 (2 CTAs/SM)
    cudaFuncSetAttribute(gemm_out, cudaFuncAttributeMaxDynamicSharedMemorySize, out_smem);
    const int attn_smem = 3 * STB;                 // 96768 (2 CTAs/SM)
    cudaFuncSetAttribute(attn_mma, cudaFuncAttributeMaxDynamicSharedMemorySize, attn_smem);

    // 1) All conversions in one launch
    conv_all<<<5376, 256>>>((const float4*)query,
                            (const float4*)Wq, (const float4*)Wk,
                            (const float4*)Wv, (const float4*)Wo,
                            (uint2*)ahi, (uint2*)alo, (uint2*)qf16,
                            (uint2*)whi, (uint2*)wlo, (uint2*)wf16);

    // 2) Q, K, V projections in one launch (z=0,1: bf3; z=2: fp16 V)
    proj_all<<<dim3(12, 32, 3), 256, proj_smem>>>(ahi, alo, whi, wlo,
                                                  qf16, wf16, qkh, qkl, vfp);

    // 3) Fused biased attention -> att fp16
    attn_mma<<<dim3(8, 12, 4), 256, attn_smem>>>(qkh, qkl, vfp, attw, att16);

    // 4) Output projection (single-pass fp16) -> fp32 + bias
    gemm_out<<<dim3(6, 32), 256, out_smem>>>(att16, wf16 + WELE, bo, out);
}

// round 14
// speedup vs baseline: 1.2655x; 1.0006x over previous
#include <cuda_runtime.h>
#include <cuda_bf16.h>
#include <cuda_fp16.h>
#include <math.h>
#include <cstdint>

#define TOTE (4096 * 768)
#define WELE (768 * 768)
#define AST 72     // bf16/fp16 smem row stride for 64-wide tiles (144B)
#define WSTW 36    // W fp32 smem row stride (144B)

// Scratch (allocation-free rule: __device__ globals)
__device__ __nv_bfloat16 g_ahi[TOTE];        // query hi
__device__ __nv_bfloat16 g_alo[TOTE];        // query lo
__device__ __half        g_qf16[TOTE];       // query fp16 (for V projection)
__device__ __nv_bfloat16 g_whi[2 * WELE];    // Wq|Wk hi
__device__ __nv_bfloat16 g_wlo[2 * WELE];    // Wq|Wk lo
__device__ __half        g_wf16[2 * WELE];   // Wv|Wo fp16
__device__ __nv_bfloat16 g_qkh[2 * TOTE];    // Q|K hi
__device__ __nv_bfloat16 g_qkl[2 * TOTE];    // Q|K lo
__device__ __half        g_vf[TOTE];         // V fp16
__device__ __half        g_att16[TOTE];      // attention output fp16

// ===========================================================================
// Base-sm_103-safe helpers (no tcgen05: ptxas virtual target is compute_103)
// ===========================================================================
__device__ __forceinline__ uint32_t smem_u32(const void* p) {
    uint32_t a;
    asm("{ .reg .u64 t; cvta.to.shared.u64 t, %1; cvt.u32.u64 %0, t; }" : "=r"(a) : "l"(p));
    return a;
}
__device__ __forceinline__ void ldsm_x4(uint32_t* r, uint32_t addr) {
    asm volatile("ldmatrix.sync.aligned.m8n8.x4.shared.b16 {%0,%1,%2,%3}, [%4];"
                 : "=r"(r[0]), "=r"(r[1]), "=r"(r[2]), "=r"(r[3]) : "r"(addr));
}
__device__ __forceinline__ void ldsm_x4_t(uint32_t* r, uint32_t addr) {
    asm volatile("ldmatrix.sync.aligned.m8n8.x4.trans.shared.b16 {%0,%1,%2,%3}, [%4];"
                 : "=r"(r[0]), "=r"(r[1]), "=r"(r[2]), "=r"(r[3]) : "r"(addr));
}
__device__ __forceinline__ void mma_bf(float* d, const uint32_t* a, uint32_t b0, uint32_t b1) {
    asm volatile(
        "mma.sync.aligned.m16n8k16.row.col.f32.bf16.bf16.f32 "
        "{%0,%1,%2,%3}, {%4,%5,%6,%7}, {%8,%9}, {%0,%1,%2,%3};"
        : "+f"(d[0]), "+f"(d[1]), "+f"(d[2]), "+f"(d[3])
        : "r"(a[0]), "r"(a[1]), "r"(a[2]), "r"(a[3]), "r"(b0), "r"(b1));
}
__device__ __forceinline__ void mma_f16(float* d, const uint32_t* a, uint32_t b0, uint32_t b1) {
    asm volatile(
        "mma.sync.aligned.m16n8k16.row.col.f32.f16.f16.f32 "
        "{%0,%1,%2,%3}, {%4,%5,%6,%7}, {%8,%9}, {%0,%1,%2,%3};"
        : "+f"(d[0]), "+f"(d[1]), "+f"(d[2]), "+f"(d[3])
        : "r"(a[0]), "r"(a[1]), "r"(a[2]), "r"(a[3]), "r"(b0), "r"(b1));
}
__device__ __forceinline__ uint32_t pack_f16x2(float lo, float hi) {
    uint32_t d;
    asm("cvt.rn.f16x2.f32 %0, %1, %2;" : "=r"(d) : "f"(hi), "f"(lo));
    return d;
}
__device__ __forceinline__ void cpa16(uint32_t dst, const void* src) {
    asm volatile("cp.async.cg.shared.global [%0], [%1], 16;" :: "r"(dst), "l"(src) : "memory");
}

// ===========================================================================
// Fused conversion kernel (one launch).
// bid ranges: [0,3072) query->hi/lo+fp16 | [3072,4224) Wq/Wk->hi/lo |
//             [4224,5376) Wv/Wo->fp16
// ===========================================================================
__global__ __launch_bounds__(256) void conv_all(
    const float4* __restrict__ q,
    const float4* __restrict__ Wq, const float4* __restrict__ Wk,
    const float4* __restrict__ Wv, const float4* __restrict__ Wo,
    uint2* __restrict__ ahi, uint2* __restrict__ alo, uint2* __restrict__ qf16,
    uint2* __restrict__ whi, uint2* __restrict__ wlo, uint2* __restrict__ wf16)
{
    const int bid = blockIdx.x;
    const int tid = threadIdx.x;
    if (bid < 3072) {
        int i = bid * 256 + tid;                   // < TOTE/4
        float4 v = q[i];
        float vv[4] = {v.x, v.y, v.z, v.w};
        __nv_bfloat16 h[4], l[4];
        __half f[4];
#pragma unroll
        for (int j = 0; j < 4; j++) {
            h[j] = __float2bfloat16(vv[j]);
            l[j] = __float2bfloat16(vv[j] - __bfloat162float(h[j]));
            f[j] = __float2half_rn(vv[j]);
        }
        ahi[i] = *(uint2*)h;
        alo[i] = *(uint2*)l;
        qf16[i] = *(uint2*)f;
    } else if (bid < 4224) {
        int r = bid - 3072;
        int zz = r / 576;
        int i = (r % 576) * 256 + tid;             // < WELE/4
        const float4* src = zz ? Wk : Wq;
        float4 v = src[i];
        float vv[4] = {v.x, v.y, v.z, v.w};
        __nv_bfloat16 h[4], l[4];
#pragma unroll
        for (int j = 0; j < 4; j++) {
            h[j] = __float2bfloat16(vv[j]);
            l[j] = __float2bfloat16(vv[j] - __bfloat162float(h[j]));
        }
        whi[(size_t)zz * (WELE / 4) + i] = *(uint2*)h;
        wlo[(size_t)zz * (WELE / 4) + i] = *(uint2*)l;
    } else {
        int r = bid - 4224;
        int zz = r / 576;
        int i = (r % 576) * 256 + tid;
        const float4* src = zz ? Wo : Wv;
        float4 v = src[i];
        __half f[4] = {__float2half_rn(v.x), __float2half_rn(v.y),
                       __float2half_rn(v.z), __float2half_rn(v.w)};
        wf16[(size_t)zz * (WELE / 4) + i] = *(uint2*)f;
    }
}

// ===========================================================================
// Fused projection kernel: one launch computes Q, K (3-term split-bf16,
// tile 128x64, 2-stage) AND V (single-pass fp16, tile 128x128, 3-stage).
// 3*FSTB == 2*GSTB == 110592 B: both paths use the same smem footprint,
// 2 CTAs/SM. ONE barrier per chunk in both paths.
// ===========================================================================
#define GTA (128 * AST * 2)          // A array bytes/stage (18432)
#define GTB (64 * AST * 2)           // B array bytes/stage (9216)
#define GSTB (2 * GTA + 2 * GTB)     // bf3 stage stride (55296)
#define FTA (128 * AST * 2)          // f16 array bytes/stage (18432)
#define FSTB (2 * FTA)               // f16 stage stride (36864)

__global__ __launch_bounds__(256, 2) void proj_all(
    const __nv_bfloat16* __restrict__ Ahi, const __nv_bfloat16* __restrict__ Alo,
    const __nv_bfloat16* __restrict__ Whi, const __nv_bfloat16* __restrict__ Wlo,
    const __half* __restrict__ Af, const __half* __restrict__ Bf,
    __nv_bfloat16* __restrict__ Chi, __nv_bfloat16* __restrict__ Clo,
    __half* __restrict__ Ch)
{
    extern __shared__ __align__(16) char smraw[];
    const uint32_t sb = smem_u32(smraw);
    const int tid = threadIdx.x, wid = tid >> 5, lane = tid & 31;
    const int z = blockIdx.z;

    if (z == 2) {
        // ---------- V projection: single-pass fp16, 128x128, 3-stage -------
        if (blockIdx.x >= 6) return;
        const int wm = (wid >> 1) * 32, wn = (wid & 1) * 64;
        const int m0 = blockIdx.y * 128, n0 = blockIdx.x * 128;
        const __half* gA = Af + (size_t)m0 * 768;
        const __half* gB = Bf + (size_t)n0 * 768;

        float acc[2][8][4];
#pragma unroll
        for (int i = 0; i < 2; i++)
#pragma unroll
            for (int j = 0; j < 8; j++)
#pragma unroll
                for (int k = 0; k < 4; k++) acc[i][j][k] = 0.f;

#define FSTAGE(buf, c_)                                                        \
    {                                                                          \
        uint32_t base_ = sb + (buf) * FSTB;                                    \
        const int k0_ = (c_) * 64;                                             \
        _Pragma("unroll")                                                      \
        for (int it = 0; it < 4; it++) {                                       \
            int idx = it * 256 + tid;                                          \
            int row = idx >> 3, cc = idx & 7;                                  \
            uint32_t off = (uint32_t)(row * AST + cc * 8) * 2;                 \
            size_t go = (size_t)row * 768 + k0_ + cc * 8;                      \
            cpa16(base_ + off,       gA + go);                                 \
            cpa16(base_ + FTA + off, gB + go);                                 \
        }                                                                      \
        asm volatile("cp.async.commit_group;" ::: "memory");                   \
    }

        FSTAGE(0, 0); FSTAGE(1, 1);
        const int lrow = lane & 15, lcol8 = (lane >> 4) * 8;
        const uint32_t offA = (uint32_t)((wm + lrow) * AST + lcol8) * 2;
        const uint32_t offB = (uint32_t)((wn + lrow) * AST + lcol8) * 2;

        for (int c = 0; c < 12; c++) {
            if (c + 2 < 12) {
                asm volatile("cp.async.wait_group 1;" ::: "memory");
            } else {
                asm volatile("cp.async.wait_group 0;" ::: "memory");
            }
            __syncthreads();
            if (c + 2 < 12) FSTAGE((c + 2) % 3, c + 2);   // buf read at c-1: safe
            uint32_t base = sb + (c % 3) * FSTB;
            uint32_t aA = base + offA, aB = base + FTA + offB;
#pragma unroll
            for (int kk = 0; kk < 4; kk++) {
                const uint32_t koff = kk * 32;
                uint32_t af[2][4];
#pragma unroll
                for (int mf = 0; mf < 2; mf++)
                    ldsm_x4(af[mf], aA + mf * 16 * AST * 2 + koff);
#pragma unroll
                for (int nq = 0; nq < 4; nq++) {
                    uint32_t bq[4];
                    ldsm_x4(bq, aB + nq * 16 * AST * 2 + koff);
#pragma unroll
                    for (int mf = 0; mf < 2; mf++) {
                        mma_f16(acc[mf][nq * 2 + 0], af[mf], bq[0], bq[2]);
                        mma_f16(acc[mf][nq * 2 + 1], af[mf], bq[1], bq[3]);
                    }
                }
            }
        }

#pragma unroll
        for (int mf = 0; mf < 2; mf++) {
#pragma unroll
            for (int nf = 0; nf < 8; nf++) {
                int row = m0 + wm + mf * 16 + (lane >> 2);
                int col = n0 + wn + nf * 8 + (lane & 3) * 2;
                __half2 h0 = __floats2half2_rn(acc[mf][nf][0], acc[mf][nf][1]);
                __half2 h1 = __floats2half2_rn(acc[mf][nf][2], acc[mf][nf][3]);
                *(uint32_t*)(Ch + (size_t)row * 768 + col) = *(uint32_t*)&h0;
                *(uint32_t*)(Ch + (size_t)(row + 8) * 768 + col) = *(uint32_t*)&h1;
            }
        }
        return;
    }

    // ---------------- Q,K projections: 3-term split-bf16, 128x64 ----------
    const int wm = (wid >> 1) * 32, wn = (wid & 1) * 32;
    const int m0 = blockIdx.y * 128, n0 = blockIdx.x * 64;

    const __nv_bfloat16* gAh = Ahi + (size_t)m0 * 768;
    const __nv_bfloat16* gAl = Alo + (size_t)m0 * 768;
    const __nv_bfloat16* gBh = Whi + (size_t)z * WELE + (size_t)n0 * 768;
    const __nv_bfloat16* gBl = Wlo + (size_t)z * WELE + (size_t)n0 * 768;

    float acc[2][4][4];
#pragma unroll
    for (int i = 0; i < 2; i++)
#pragma unroll
        for (int j = 0; j < 4; j++)
#pragma unroll
            for (int k = 0; k < 4; k++) acc[i][j][k] = 0.f;

#define GSTAGE(buf, c_)                                                        \
    {                                                                          \
        uint32_t base_ = sb + (buf) * GSTB;                                    \
        const int k0_ = (c_) * 64;                                             \
        _Pragma("unroll")                                                      \
        for (int it = 0; it < 4; it++) {                                       \
            int idx = it * 256 + tid;                                          \
            int row = idx >> 3, cc = idx & 7;                                  \
            uint32_t off = (uint32_t)(row * AST + cc * 8) * 2;                 \
            size_t go = (size_t)row * 768 + k0_ + cc * 8;                      \
            cpa16(base_ + off,       gAh + go);                                \
            cpa16(base_ + GTA + off, gAl + go);                                \
        }                                                                      \
        _Pragma("unroll")                                                      \
        for (int it = 0; it < 2; it++) {                                       \
            int idx = it * 256 + tid;                                          \
            int row = idx >> 3, cc = idx & 7;                                  \
            uint32_t off = (uint32_t)(row * AST + cc * 8) * 2;                 \
            size_t go = (size_t)row * 768 + k0_ + cc * 8;                      \
            cpa16(base_ + 2 * GTA + off,       gBh + go);                      \
            cpa16(base_ + 2 * GTA + GTB + off, gBl + go);                      \
        }                                                                      \
        asm volatile("cp.async.commit_group;" ::: "memory");                   \
    }

    GSTAGE(0, 0);

    const int lrow = lane & 15, lcol8 = (lane >> 4) * 8;
    const uint32_t offA = (uint32_t)((wm + lrow) * AST + lcol8) * 2;
    const uint32_t offB = (uint32_t)((wn + lrow) * AST + lcol8) * 2;

    for (int c = 0; c < 12; c++) {
        asm volatile("cp.async.wait_group 0;" ::: "memory");
        __syncthreads();
        if (c + 1 < 12) GSTAGE((c + 1) & 1, c + 1);
        uint32_t base = sb + (c & 1) * GSTB;
        uint32_t aAh = base + offA, aAl = base + GTA + offA;
        uint32_t aBh = base + 2 * GTA + offB, aBl = base + 2 * GTA + GTB + offB;
#pragma unroll
        for (int kk = 0; kk < 4; kk++) {
            const uint32_t koff = kk * 32;
            uint32_t ah[2][4], al[2][4], bh[2][4], bl[2][4];
#pragma unroll
            for (int mf = 0; mf < 2; mf++) {
                ldsm_x4(ah[mf], aAh + mf * 16 * AST * 2 + koff);
                ldsm_x4(al[mf], aAl + mf * 16 * AST * 2 + koff);
            }
#pragma unroll
            for (int nq = 0; nq < 2; nq++) {
                ldsm_x4(bh[nq], aBh + nq * 16 * AST * 2 + koff);
                ldsm_x4(bl[nq], aBl + nq * 16 * AST * 2 + koff);
            }
#pragma unroll
            for (int mf = 0; mf < 2; mf++) {
#pragma unroll
                for (int nq = 0; nq < 2; nq++) {
                    float* a0 = acc[mf][nq * 2 + 0];
                    float* a1 = acc[mf][nq * 2 + 1];
                    mma_bf(a0, ah[mf], bh[nq][0], bh[nq][2]);
                    mma_bf(a1, ah[mf], bh[nq][1], bh[nq][3]);
                    mma_bf(a0, al[mf], bh[nq][0], bh[nq][2]);
                    mma_bf(a1, al[mf], bh[nq][1], bh[nq][3]);
                    mma_bf(a0, ah[mf], bl[nq][0], bl[nq][2]);
                    mma_bf(a1, ah[mf], bl[nq][1], bl[nq][3]);
                }
            }
        }
    }

#pragma unroll
    for (int mf = 0; mf < 2; mf++) {
#pragma unroll
        for (int nf = 0; nf < 4; nf++) {
            int row = m0 + wm + mf * 16 + (lane >> 2);
            int col = n0 + wn + nf * 8 + (lane & 3) * 2;
            float v0 = acc[mf][nf][0], v1 = acc[mf][nf][1];
            float v2 = acc[mf][nf][2], v3 = acc[mf][nf][3];
            __nv_bfloat16* ch = Chi + (size_t)z * TOTE;
            __nv_bfloat16* cl = Clo + (size_t)z * TOTE;
            __nv_bfloat16 h0 = __float2bfloat16(v0), h1 = __float2bfloat16(v1);
            __nv_bfloat16 h2 = __float2bfloat16(v2), h3 = __float2bfloat16(v3);
            __nv_bfloat162 ph0 = {h0, h1}, ph1 = {h2, h3};
            __nv_bfloat162 pl0 = {__float2bfloat16(v0 - __bfloat162float(h0)),
                                  __float2bfloat16(v1 - __bfloat162float(h1))};
            __nv_bfloat162 pl1 = {__float2bfloat16(v2 - __bfloat162float(h2)),
                                  __float2bfloat16(v3 - __bfloat162float(h3))};
            *(uint32_t*)(ch + (size_t)row * 768 + col) = *(uint32_t*)&ph0;
            *(uint32_t*)(ch + (size_t)(row + 8) * 768 + col) = *(uint32_t*)&ph1;
            *(uint32_t*)(cl + (size_t)row * 768 + col) = *(uint32_t*)&pl0;
            *(uint32_t*)(cl + (size_t)(row + 8) * 768 + col) = *(uint32_t*)&pl1;
        }
    }
}

// ===========================================================================
// Output projection: single-pass fp16 NT GEMM, fp32 + bias epilogue.
// Block tile 128x128, K-chunk 64, 3-stage cp.async, ONE barrier per chunk,
// 2 CTAs/SM (3*FSTB = 110592 B).
// ===========================================================================
__global__ __launch_bounds__(256, 2) void gemm_out(
    const __half* __restrict__ Af, const __half* __restrict__ Bf,
    const float* __restrict__ bias, float* __restrict__ Cf)
{
    extern __shared__ __align__(16) __half smh[];
    const uint32_t sb = smem_u32(smh);

    const int tid = threadIdx.x, wid = tid >> 5, lane = tid & 31;
    const int wm = (wid >> 1) * 32, wn = (wid & 1) * 64;
    const int m0 = blockIdx.y * 128, n0 = blockIdx.x * 128;

    const __half* gA = Af + (size_t)m0 * 768;
    const __half* gB = Bf + (size_t)n0 * 768;

    float acc[2][8][4];
#pragma unroll
    for (int i = 0; i < 2; i++)
#pragma unroll
        for (int j = 0; j < 8; j++)
#pragma unroll
            for (int k = 0; k < 4; k++) acc[i][j][k] = 0.f;

#define OSTAGE(buf, c_)                                                        \
    {                                                                          \
        uint32_t base_ = sb + (buf) * FSTB;                                    \
        const int k0_ = (c_) * 64;                                             \
        _Pragma("unroll")                                                      \
        for (int it = 0; it < 4; it++) {                                       \
            int idx = it * 256 + tid;                                          \
            int row = idx >> 3, cc = idx & 7;                                  \
            uint32_t off = (uint32_t)(row * AST + cc * 8) * 2;                 \
            size_t go = (size_t)row * 768 + k0_ + cc * 8;                      \
            cpa16(base_ + off,       gA + go);                                 \
            cpa16(base_ + FTA + off, gB + go);                                 \
        }                                                                      \
        asm volatile("cp.async.commit_group;" ::: "memory");                   \
    }

    OSTAGE(0, 0); OSTAGE(1, 1);

    const int lrow = lane & 15, lcol8 = (lane >> 4) * 8;
    const uint32_t offA = (uint32_t)((wm + lrow) * AST + lcol8) * 2;
    const uint32_t offB = (uint32_t)((wn + lrow) * AST + lcol8) * 2;

    for (int c = 0; c < 12; c++) {
        if (c + 2 < 12) {
            asm volatile("cp.async.wait_group 1;" ::: "memory");
        } else {
            asm volatile("cp.async.wait_group 0;" ::: "memory");
        }
        __syncthreads();
        if (c + 2 < 12) OSTAGE((c + 2) % 3, c + 2);   // buf read at c-1: safe
        uint32_t base = sb + (c % 3) * FSTB;
        uint32_t aA = base + offA, aB = base + FTA + offB;
#pragma unroll
        for (int kk = 0; kk < 4; kk++) {
            const uint32_t koff = kk * 32;
            uint32_t af[2][4];
#pragma unroll
            for (int mf = 0; mf < 2; mf++)
                ldsm_x4(af[mf], aA + mf * 16 * AST * 2 + koff);
#pragma unroll
            for (int nq = 0; nq < 4; nq++) {
                uint32_t bq[4];
                ldsm_x4(bq, aB + nq * 16 * AST * 2 + koff);
#pragma unroll
                for (int mf = 0; mf < 2; mf++) {
                    mma_f16(acc[mf][nq * 2 + 0], af[mf], bq[0], bq[2]);
                    mma_f16(acc[mf][nq * 2 + 1], af[mf], bq[1], bq[3]);
                }
            }
        }
    }

#pragma unroll
    for (int mf = 0; mf < 2; mf++) {
#pragma unroll
        for (int nf = 0; nf < 8; nf++) {
            int row = m0 + wm + mf * 16 + (lane >> 2);
            int col = n0 + wn + nf * 8 + (lane & 3) * 2;
            float b0 = bias[col], b1 = bias[col + 1];
            *(float2*)(Cf + (size_t)row * 768 + col) =
                make_float2(acc[mf][nf][0] + b0, acc[mf][nf][1] + b1);
            *(float2*)(Cf + (size_t)(row + 8) * 768 + col) =
                make_float2(acc[mf][nf][2] + b0, acc[mf][nf][3] + b1);
        }
    }
}

// ===========================================================================
// HMMA fused biased flash attention (no-max softmax).
// Key tile 32, 3-stage cp.async pipeline (K hi/lo + V + W), 2 CTAs/SM.
// ===========================================================================
#define KT 32
#define KVB (KT * AST * 2)            // 4608 B per K/V array per stage
#define WB  (128 * WSTW * 4)          // 18432 B W tile per stage
#define STB (3 * KVB + WB)            // stage stride 32256 B

__global__ __launch_bounds__(256, 2) void attn_mma(
    const __nv_bfloat16* __restrict__ qkh, const __nv_bfloat16* __restrict__ qkl,
    const __half* __restrict__ vf, const float* __restrict__ W,
    __half* __restrict__ att16)
{
    extern __shared__ __align__(16) char smn[];
    const uint32_t sb = smem_u32(smn);

    const int tid = threadIdx.x, wp = tid >> 5, lane = tid & 31;
    const int n0 = blockIdx.x * 128, h = blockIdx.y, b = blockIdx.z;

    const __nv_bfloat16* qh = qkh + ((size_t)(b * 1024 + n0)) * 768 + h * 64;
    const __nv_bfloat16* ql = qkl + ((size_t)(b * 1024 + n0)) * 768 + h * 64;
    const __nv_bfloat16* kh = qkh + (size_t)TOTE + (size_t)b * 1024 * 768 + h * 64;
    const __nv_bfloat16* kl = qkl + (size_t)TOTE + (size_t)b * 1024 * 768 + h * 64;
    const __half* vg = vf + (size_t)b * 1024 * 768 + h * 64;
    const float* wg = W + ((size_t)(b * 12 + h) * 1024 + n0) * 1024;

    // --- Stage Q (128x64) hi/lo through smem (pre-pipeline), frags to regs ---
    {
        __nv_bfloat16* tQh = (__nv_bfloat16*)smn;
        __nv_bfloat16* tQl = tQh + 128 * AST;
#pragma unroll
        for (int it = 0; it < 4; it++) {
            int idx = it * 256 + tid;
            int row = idx >> 3, cc = idx & 7;
            *(uint4*)(tQh + row * AST + cc * 8) = *(const uint4*)(qh + (size_t)row * 768 + cc * 8);
            *(uint4*)(tQl + row * AST + cc * 8) = *(const uint4*)(ql + (size_t)row * 768 + cc * 8);
        }
    }
    __syncthreads();
    uint32_t qfh[4][4], qfl[4][4];
    {
        uint32_t off = (uint32_t)((wp * 16 + (lane & 15)) * AST + (lane >> 4) * 8) * 2;
#pragma unroll
        for (int ks = 0; ks < 4; ks++) {
            ldsm_x4(qfh[ks], sb + off + ks * 32);
            ldsm_x4(qfl[ks], sb + 128 * AST * 2 + off + ks * 32);
        }
    }
    __syncthreads();

    float oacc[8][4];
#pragma unroll
    for (int d = 0; d < 8; d++)
#pragma unroll
        for (int j = 0; j < 4; j++) oacc[d][j] = 0.f;
    float l0r = 0.f, l1r = 0.f;

#define ASTAGE(buf, t_)                                                        \
    {                                                                          \
        uint32_t base_ = sb + (buf) * STB;                                     \
        const int s0_ = (t_) * KT;                                             \
        {                                                                      \
            int row = tid >> 3, cc = tid & 7;                                  \
            uint32_t doff = (uint32_t)(row * AST + cc * 8) * 2;                \
            size_t go = (size_t)(s0_ + row) * 768 + cc * 8;                    \
            cpa16(base_ + doff,           kh + go);                            \
            cpa16(base_ + KVB + doff,     kl + go);                            \
            cpa16(base_ + 2 * KVB + doff, vg + go);                            \
        }                                                                      \
        _Pragma("unroll")                                                      \
        for (int it = 0; it < 4; it++) {                                       \
            int idx = it * 256 + tid;                                          \
            int row = idx >> 3, cc = idx & 7;                                  \
            cpa16(base_ + 3 * KVB + (uint32_t)(row * WSTW + cc * 4) * 4,       \
                  wg + (size_t)row * 1024 + s0_ + cc * 4);                     \
        }                                                                      \
        asm volatile("cp.async.commit_group;" ::: "memory");                   \
    }

    ASTAGE(0, 0); ASTAGE(1, 1);

    const uint32_t foff = (uint32_t)(((lane & 15) * AST) + (lane >> 4) * 8) * 2;
    const int c0 = (lane & 3) * 2;
    const uint32_t woff = (uint32_t)((wp * 16 + (lane >> 2)) * WSTW + c0) * 4;

    for (int t = 0; t < 32; t++) {
        if (t + 2 < 32) {
            asm volatile("cp.async.wait_group 1;" ::: "memory");
        } else {
            asm volatile("cp.async.wait_group 0;" ::: "memory");
        }
        __syncthreads();
        if (t + 2 < 32) ASTAGE((t + 2) % 3, t + 2);
        uint32_t base = sb + (t % 3) * STB;
        uint32_t kbh = base + foff, kbl = base + KVB + foff;
        uint32_t vbb = base + 2 * KVB + foff;
        uint32_t wb0 = base + 3 * KVB + woff;

        // ---- S = Q K^T (3-term split-bf16), 32 keys ----
        float sc[4][4];
#pragma unroll
        for (int nf = 0; nf < 4; nf++)
#pragma unroll
            for (int j = 0; j < 4; j++) sc[nf][j] = 0.f;
#pragma unroll
        for (int nf2 = 0; nf2 < 2; nf2++) {
#pragma unroll
            for (int ks = 0; ks < 4; ks++) {
                uint32_t off = (uint32_t)(nf2 * 16 * AST + ks * 16) * 2;
                uint32_t fh[4], fl[4];
                ldsm_x4(fh, kbh + off);
                ldsm_x4(fl, kbl + off);
                mma_bf(sc[2 * nf2],     qfh[ks], fh[0], fh[2]);
                mma_bf(sc[2 * nf2 + 1], qfh[ks], fh[1], fh[3]);
                mma_bf(sc[2 * nf2],     qfl[ks], fh[0], fh[2]);
                mma_bf(sc[2 * nf2 + 1], qfl[ks], fh[1], fh[3]);
                mma_bf(sc[2 * nf2],     qfh[ks], fl[0], fl[2]);
                mma_bf(sc[2 * nf2 + 1], qfh[ks], fl[1], fl[3]);
            }
        }

        // ---- p = exp(W + scale*S) directly (bounded logits, no max) ----
        float rs0 = 0.f, rs1 = 0.f;
#pragma unroll
        for (int nf = 0; nf < 4; nf++) {
            float2 w0, w1;
            asm volatile("ld.shared.v2.f32 {%0,%1}, [%2];"
                         : "=f"(w0.x), "=f"(w0.y) : "r"(wb0 + nf * 32));
            asm volatile("ld.shared.v2.f32 {%0,%1}, [%2];"
                         : "=f"(w1.x), "=f"(w1.y) : "r"(wb0 + 8 * WSTW * 4 + nf * 32));
            sc[nf][0] = __expf(fmaf(sc[nf][0], 0.125f, w0.x));
            sc[nf][1] = __expf(fmaf(sc[nf][1], 0.125f, w0.y));
            sc[nf][2] = __expf(fmaf(sc[nf][2], 0.125f, w1.x));
            sc[nf][3] = __expf(fmaf(sc[nf][3], 0.125f, w1.y));
            rs0 += sc[nf][0] + sc[nf][1];
            rs1 += sc[nf][2] + sc[nf][3];
        }
        l0r += rs0;
        l1r += rs1;

        // ---- out += P V (fp16, P from registers) ----
#pragma unroll
        for (int kc = 0; kc < 2; kc++) {
            uint32_t pa[4];
            pa[0] = pack_f16x2(sc[2 * kc][0], sc[2 * kc][1]);
            pa[1] = pack_f16x2(sc[2 * kc][2], sc[2 * kc][3]);
            pa[2] = pack_f16x2(sc[2 * kc + 1][0], sc[2 * kc + 1][1]);
            pa[3] = pack_f16x2(sc[2 * kc + 1][2], sc[2 * kc + 1][3]);
#pragma unroll
            for (int dp = 0; dp < 4; dp++) {
                uint32_t vf4[4];
                ldsm_x4_t(vf4, vbb + (uint32_t)(kc * 16 * AST + dp * 16) * 2);
                mma_f16(oacc[2 * dp],     pa, vf4[0], vf4[1]);
                mma_f16(oacc[2 * dp + 1], pa, vf4[2], vf4[3]);
            }
        }
    }

    // ---- normalize + write fp16 (att layout [4096, 768]) ----
    l0r += __shfl_xor_sync(0xffffffffu, l0r, 1);
    l0r += __shfl_xor_sync(0xffffffffu, l0r, 2);
    l1r += __shfl_xor_sync(0xffffffffu, l1r, 1);
    l1r += __shfl_xor_sync(0xffffffffu, l1r, 2);
    float i0 = 1.f / l0r, i1 = 1.f / l1r;
    int row = b * 1024 + n0 + wp * 16 + (lane >> 2);
    int colb = h * 64 + c0;
#pragma unroll
    for (int d = 0; d < 8; d++) {
        __half2 h0 = __floats2half2_rn(oacc[d][0] * i0, oacc[d][1] * i0);
        __half2 h1 = __floats2half2_rn(oacc[d][2] * i1, oacc[d][3] * i1);
        *(uint32_t*)(att16 + (size_t)row * 768 + colb + d * 8) = *(uint32_t*)&h0;
        *(uint32_t*)(att16 + (size_t)(row + 8) * 768 + colb + d * 8) = *(uint32_t*)&h1;
    }
}

// ===========================================================================
// Launch
// ===========================================================================
extern "C" void kernel_launch(void* const* d_in, const int* in_sizes, int n_in,
                              void* d_out, int out_size)
{
    const float* query = (const float*)d_in[0];
    const float* attw  = (const float*)d_in[1];
    const float* Wq    = (const float*)d_in[2];
    const float* Wk    = (const float*)d_in[3];
    const float* Wv    = (const float*)d_in[4];
    const float* Wo    = (const float*)d_in[5];
    const float* bo    = (const float*)d_in[6];
    float* out = (float*)d_out;

    __nv_bfloat16 *ahi, *alo, *whi, *wlo, *qkh, *qkl;
    __half *qf16, *wf16, *vfp, *att16;
    cudaGetSymbolAddress((void**)&ahi, g_ahi);
    cudaGetSymbolAddress((void**)&alo, g_alo);
    cudaGetSymbolAddress((void**)&qf16, g_qf16);
    cudaGetSymbolAddress((void**)&whi, g_whi);
    cudaGetSymbolAddress((void**)&wlo, g_wlo);
    cudaGetSymbolAddress((void**)&wf16, g_wf16);
    cudaGetSymbolAddress((void**)&qkh, g_qkh);
    cudaGetSymbolAddress((void**)&qkl, g_qkl);
    cudaGetSymbolAddress((void**)&vfp, g_vf);
    cudaGetSymbolAddress((void**)&att16, g_att16);

    const int proj_smem = 2 * GSTB;                // 110592 == 3*FSTB (2 CTAs/SM)
    cudaFuncSetAttribute(proj_all, cudaFuncAttributeMaxDynamicSharedMemorySize, proj_smem);
    const int out_smem = 3 * FSTB;                 // 110592 (2 CTAs/SM)
    cudaFuncSetAttribute(gemm_out, cudaFuncAttributeMaxDynamicSharedMemorySize, out_smem);
    const int attn_smem = 3 * STB;                 // 96768 (2 CTAs/SM)
    cudaFuncSetAttribute(attn_mma, cudaFuncAttributeMaxDynamicSharedMemorySize, attn_smem);

    // 1) All conversions in one launch
    conv_all<<<5376, 256>>>((const float4*)query,
                            (const float4*)Wq, (const float4*)Wk,
                            (const float4*)Wv, (const float4*)Wo,
                            (uint2*)ahi, (uint2*)alo, (uint2*)qf16,
                            (uint2*)whi, (uint2*)wlo, (uint2*)wf16);

    // 2) Q, K, V projections in one launch (z=0,1: bf3; z=2: fp16 V 3-stage)
    proj_all<<<dim3(12, 32, 3), 256, proj_smem>>>(ahi, alo, whi, wlo,
                                                  qf16, wf16, qkh, qkl, vfp);

    // 3) Fused biased attention -> att fp16
    attn_mma<<<dim3(8, 12, 4), 256, attn_smem>>>(qkh, qkl, vfp, attw, att16);

    // 4) Output projection (single-pass fp16, 3-stage) -> fp32 + bias
    gemm_out<<<dim3(6, 32), 256, out_smem>>>(att16, wf16 + WELE, bo, out);
}

// round 15
// speedup vs baseline: 2.1758x; 1.7193x over previous
#include <cuda_runtime.h>
#include <cuda_fp16.h>
#include <math.h>
#include <cstdint>

#define TOTE (4096 * 768)
#define WELE (768 * 768)
#define AST 72     // fp16 smem row stride for 64-wide tiles (144B)
#define WSTW 36    // W fp32 smem row stride (144B)

// Scratch (allocation-free rule: __device__ globals)
__device__ __half g_qf16[TOTE];        // query fp16
__device__ __half g_wf16[4 * WELE];    // Wq|Wk|Wv|Wo fp16
__device__ __half g_qk16[2 * TOTE];    // Q|K fp16
__device__ __half g_vf[TOTE];          // V fp16
__device__ __half g_att16[TOTE];       // attention output fp16

// ===========================================================================
// Base-sm_103-safe helpers (no tcgen05: ptxas virtual target is compute_103)
// ===========================================================================
__device__ __forceinline__ uint32_t smem_u32(const void* p) {
    uint32_t a;
    asm("{ .reg .u64 t; cvta.to.shared.u64 t, %1; cvt.u32.u64 %0, t; }" : "=r"(a) : "l"(p));
    return a;
}
__device__ __forceinline__ void ldsm_x4(uint32_t* r, uint32_t addr) {
    asm volatile("ldmatrix.sync.aligned.m8n8.x4.shared.b16 {%0,%1,%2,%3}, [%4];"
                 : "=r"(r[0]), "=r"(r[1]), "=r"(r[2]), "=r"(r[3]) : "r"(addr));
}
__device__ __forceinline__ void ldsm_x4_t(uint32_t* r, uint32_t addr) {
    asm volatile("ldmatrix.sync.aligned.m8n8.x4.trans.shared.b16 {%0,%1,%2,%3}, [%4];"
                 : "=r"(r[0]), "=r"(r[1]), "=r"(r[2]), "=r"(r[3]) : "r"(addr));
}
__device__ __forceinline__ void mma_f16(float* d, const uint32_t* a, uint32_t b0, uint32_t b1) {
    asm volatile(
        "mma.sync.aligned.m16n8k16.row.col.f32.f16.f16.f32 "
        "{%0,%1,%2,%3}, {%4,%5,%6,%7}, {%8,%9}, {%0,%1,%2,%3};"
        : "+f"(d[0]), "+f"(d[1]), "+f"(d[2]), "+f"(d[3])
        : "r"(a[0]), "r"(a[1]), "r"(a[2]), "r"(a[3]), "r"(b0), "r"(b1));
}
__device__ __forceinline__ uint32_t pack_f16x2(float lo, float hi) {
    uint32_t d;
    asm("cvt.rn.f16x2.f32 %0, %1, %2;" : "=r"(d) : "f"(hi), "f"(lo));
    return d;
}
__device__ __forceinline__ void cpa16(uint32_t dst, const void* src) {
    asm volatile("cp.async.cg.shared.global [%0], [%1], 16;" :: "r"(dst), "l"(src) : "memory");
}

// ===========================================================================
// Fused conversion: query + all four weights -> fp16, one launch.
// bid [0,3072): query | [3072,5376): weights (zz = (bid-3072)/576)
// ===========================================================================
__global__ __launch_bounds__(256) void conv_all(
    const float4* __restrict__ q,
    const float4* __restrict__ Wq, const float4* __restrict__ Wk,
    const float4* __restrict__ Wv, const float4* __restrict__ Wo,
    uint2* __restrict__ qf16, uint2* __restrict__ wf16)
{
    const int bid = blockIdx.x;
    const int tid = threadIdx.x;
    if (bid < 3072) {
        int i = bid * 256 + tid;
        float4 v = q[i];
        __half f[4] = {__float2half_rn(v.x), __float2half_rn(v.y),
                       __float2half_rn(v.z), __float2half_rn(v.w)};
        qf16[i] = *(uint2*)f;
    } else {
        int r = bid - 3072;
        int zz = r / 576;
        int i = (r % 576) * 256 + tid;
        const float4* src = (zz == 0) ? Wq : (zz == 1) ? Wk : (zz == 2) ? Wv : Wo;
        float4 v = src[i];
        __half f[4] = {__float2half_rn(v.x), __float2half_rn(v.y),
                       __float2half_rn(v.z), __float2half_rn(v.w)};
        wf16[(size_t)zz * (WELE / 4) + i] = *(uint2*)f;
    }
}

// ===========================================================================
// Q/K/V projections: single-pass fp16 NT GEMM, one launch (z selects weight
// + output). Block tile 128x128, K-chunk 64, 3-stage cp.async, ONE barrier
// per chunk, 2 CTAs/SM. 576 equal CTAs -> near-perfect SM balance.
// ===========================================================================
#define FTA (128 * AST * 2)          // bytes per array per stage (18432)
#define FSTB (2 * FTA)               // stage stride (36864)

__global__ __launch_bounds__(256, 2) void proj_qkv(
    const __half* __restrict__ Af, const __half* __restrict__ Wf,
    __half* __restrict__ qk, __half* __restrict__ vf)
{
    extern __shared__ __align__(16) __half smh[];
    const uint32_t sb = smem_u32(smh);

    const int tid = threadIdx.x, wid = tid >> 5, lane = tid & 31;
    const int wm = (wid >> 1) * 32, wn = (wid & 1) * 64;
    const int m0 = blockIdx.y * 128, n0 = blockIdx.x * 128;
    const int z = blockIdx.z;

    const __half* gA = Af + (size_t)m0 * 768;
    const __half* gB = Wf + (size_t)z * WELE + (size_t)n0 * 768;
    __half* dst = (z == 2) ? vf : qk + (size_t)z * TOTE;

    float acc[2][8][4];
#pragma unroll
    for (int i = 0; i < 2; i++)
#pragma unroll
        for (int j = 0; j < 8; j++)
#pragma unroll
            for (int k = 0; k < 4; k++) acc[i][j][k] = 0.f;

#define PSTAGE(buf, c_)                                                        \
    {                                                                          \
        uint32_t base_ = sb + (buf) * FSTB;                                    \
        const int k0_ = (c_) * 64;                                             \
        _Pragma("unroll")                                                      \
        for (int it = 0; it < 4; it++) {                                       \
            int idx = it * 256 + tid;                                          \
            int row = idx >> 3, cc = idx & 7;                                  \
            uint32_t off = (uint32_t)(row * AST + cc * 8) * 2;                 \
            size_t go = (size_t)row * 768 + k0_ + cc * 8;                      \
            cpa16(base_ + off,       gA + go);                                 \
            cpa16(base_ + FTA + off, gB + go);                                 \
        }                                                                      \
        asm volatile("cp.async.commit_group;" ::: "memory");                   \
    }

    PSTAGE(0, 0); PSTAGE(1, 1);

    const int lrow = lane & 15, lcol8 = (lane >> 4) * 8;
    const uint32_t offA = (uint32_t)((wm + lrow) * AST + lcol8) * 2;
    const uint32_t offB = (uint32_t)((wn + lrow) * AST + lcol8) * 2;

    for (int c = 0; c < 12; c++) {
        if (c + 2 < 12) {
            asm volatile("cp.async.wait_group 1;" ::: "memory");
        } else {
            asm volatile("cp.async.wait_group 0;" ::: "memory");
        }
        __syncthreads();
        if (c + 2 < 12) PSTAGE((c + 2) % 3, c + 2);   // buf read at c-1: safe
        uint32_t base = sb + (c % 3) * FSTB;
        uint32_t aA = base + offA, aB = base + FTA + offB;
#pragma unroll
        for (int kk = 0; kk < 4; kk++) {
            const uint32_t koff = kk * 32;
            uint32_t af[2][4];
#pragma unroll
            for (int mf = 0; mf < 2; mf++)
                ldsm_x4(af[mf], aA + mf * 16 * AST * 2 + koff);
#pragma unroll
            for (int nq = 0; nq < 4; nq++) {
                uint32_t bq[4];
                ldsm_x4(bq, aB + nq * 16 * AST * 2 + koff);
#pragma unroll
                for (int mf = 0; mf < 2; mf++) {
                    mma_f16(acc[mf][nq * 2 + 0], af[mf], bq[0], bq[2]);
                    mma_f16(acc[mf][nq * 2 + 1], af[mf], bq[1], bq[3]);
                }
            }
        }
    }

#pragma unroll
    for (int mf = 0; mf < 2; mf++) {
#pragma unroll
        for (int nf = 0; nf < 8; nf++) {
            int row = m0 + wm + mf * 16 + (lane >> 2);
            int col = n0 + wn + nf * 8 + (lane & 3) * 2;
            __half2 h0 = __floats2half2_rn(acc[mf][nf][0], acc[mf][nf][1]);
            __half2 h1 = __floats2half2_rn(acc[mf][nf][2], acc[mf][nf][3]);
            *(uint32_t*)(dst + (size_t)row * 768 + col) = *(uint32_t*)&h0;
            *(uint32_t*)(dst + (size_t)(row + 8) * 768 + col) = *(uint32_t*)&h1;
        }
    }
}

// ===========================================================================
// HMMA fused biased flash attention: single-pass fp16 QK + fp16 PV,
// no-max softmax. Key tile 32, 3-stage cp.async (K + V + W), 2 CTAs/SM.
// ===========================================================================
#define KT 32
#define KVB (KT * AST * 2)            // 4608 B per K/V array per stage
#define WB  (128 * WSTW * 4)          // 18432 B W tile per stage
#define STB (2 * KVB + WB)            // stage stride 27648 B

__global__ __launch_bounds__(256, 2) void attn_mma(
    const __half* __restrict__ qk16, const __half* __restrict__ vf,
    const float* __restrict__ W, __half* __restrict__ att16)
{
    extern __shared__ __align__(16) char smn[];
    const uint32_t sb = smem_u32(smn);

    const int tid = threadIdx.x, wp = tid >> 5, lane = tid & 31;
    const int n0 = blockIdx.x * 128, h = blockIdx.y, b = blockIdx.z;

    const __half* qg = qk16 + ((size_t)(b * 1024 + n0)) * 768 + h * 64;
    const __half* kg = qk16 + (size_t)TOTE + (size_t)b * 1024 * 768 + h * 64;
    const __half* vg = vf + (size_t)b * 1024 * 768 + h * 64;
    const float* wg = W + ((size_t)(b * 12 + h) * 1024 + n0) * 1024;

    // --- Stage Q (128x64 fp16) through smem (pre-pipeline), frags to regs ---
    {
        __half* tQ = (__half*)smn;
#pragma unroll
        for (int it = 0; it < 4; it++) {
            int idx = it * 256 + tid;
            int row = idx >> 3, cc = idx & 7;
            *(uint4*)(tQ + row * AST + cc * 8) = *(const uint4*)(qg + (size_t)row * 768 + cc * 8);
        }
    }
    __syncthreads();
    uint32_t qf[4][4];
    {
        uint32_t off = (uint32_t)((wp * 16 + (lane & 15)) * AST + (lane >> 4) * 8) * 2;
#pragma unroll
        for (int ks = 0; ks < 4; ks++)
            ldsm_x4(qf[ks], sb + off + ks * 32);
    }
    __syncthreads();

    float oacc[8][4];
#pragma unroll
    for (int d = 0; d < 8; d++)
#pragma unroll
        for (int j = 0; j < 4; j++) oacc[d][j] = 0.f;
    float l0r = 0.f, l1r = 0.f;

#define ASTAGE(buf, t_)                                                        \
    {                                                                          \
        uint32_t base_ = sb + (buf) * STB;                                     \
        const int s0_ = (t_) * KT;                                             \
        {                                                                      \
            int row = tid >> 3, cc = tid & 7;                                  \
            uint32_t doff = (uint32_t)(row * AST + cc * 8) * 2;                \
            size_t go = (size_t)(s0_ + row) * 768 + cc * 8;                    \
            cpa16(base_ + doff,       kg + go);                                \
            cpa16(base_ + KVB + doff, vg + go);                                \
        }                                                                      \
        _Pragma("unroll")                                                      \
        for (int it = 0; it < 4; it++) {                                       \
            int idx = it * 256 + tid;                                          \
            int row = idx >> 3, cc = idx & 7;                                  \
            cpa16(base_ + 2 * KVB + (uint32_t)(row * WSTW + cc * 4) * 4,       \
                  wg + (size_t)row * 1024 + s0_ + cc * 4);                     \
        }                                                                      \
        asm volatile("cp.async.commit_group;" ::: "memory");                   \
    }

    ASTAGE(0, 0); ASTAGE(1, 1);

    const uint32_t foff = (uint32_t)(((lane & 15) * AST) + (lane >> 4) * 8) * 2;
    const int c0 = (lane & 3) * 2;
    const uint32_t woff = (uint32_t)((wp * 16 + (lane >> 2)) * WSTW + c0) * 4;

    for (int t = 0; t < 32; t++) {
        if (t + 2 < 32) {
            asm volatile("cp.async.wait_group 1;" ::: "memory");
        } else {
            asm volatile("cp.async.wait_group 0;" ::: "memory");
        }
        __syncthreads();
        if (t + 2 < 32) ASTAGE((t + 2) % 3, t + 2);   // stage read at t-1: safe
        uint32_t base = sb + (t % 3) * STB;
        uint32_t kbb = base + foff;
        uint32_t vbb = base + KVB + foff;
        uint32_t wb0 = base + 2 * KVB + woff;

        // ---- S = Q K^T (single-pass fp16), 32 keys ----
        float sc[4][4];
#pragma unroll
        for (int nf = 0; nf < 4; nf++)
#pragma unroll
            for (int j = 0; j < 4; j++) sc[nf][j] = 0.f;
#pragma unroll
        for (int nf2 = 0; nf2 < 2; nf2++) {
#pragma unroll
            for (int ks = 0; ks < 4; ks++) {
                uint32_t fh[4];
                ldsm_x4(fh, kbb + (uint32_t)(nf2 * 16 * AST + ks * 16) * 2);
                mma_f16(sc[2 * nf2],     qf[ks], fh[0], fh[2]);
                mma_f16(sc[2 * nf2 + 1], qf[ks], fh[1], fh[3]);
            }
        }

        // ---- p = exp(W + scale*S) directly (bounded logits, no max) ----
        float rs0 = 0.f, rs1 = 0.f;
#pragma unroll
        for (int nf = 0; nf < 4; nf++) {
            float2 w0, w1;
            asm volatile("ld.shared.v2.f32 {%0,%1}, [%2];"
                         : "=f"(w0.x), "=f"(w0.y) : "r"(wb0 + nf * 32));
            asm volatile("ld.shared.v2.f32 {%0,%1}, [%2];"
                         : "=f"(w1.x), "=f"(w1.y) : "r"(wb0 + 8 * WSTW * 4 + nf * 32));
            sc[nf][0] = __expf(fmaf(sc[nf][0], 0.125f, w0.x));
            sc[nf][1] = __expf(fmaf(sc[nf][1], 0.125f, w0.y));
            sc[nf][2] = __expf(fmaf(sc[nf][2], 0.125f, w1.x));
            sc[nf][3] = __expf(fmaf(sc[nf][3], 0.125f, w1.y));
            rs0 += sc[nf][0] + sc[nf][1];
            rs1 += sc[nf][2] + sc[nf][3];
        }
        l0r += rs0;
        l1r += rs1;

        // ---- out += P V (fp16, P from registers) ----
#pragma unroll
        for (int kc = 0; kc < 2; kc++) {
            uint32_t pa[4];
            pa[0] = pack_f16x2(sc[2 * kc][0], sc[2 * kc][1]);
            pa[1] = pack_f16x2(sc[2 * kc][2], sc[2 * kc][3]);
            pa[2] = pack_f16x2(sc[2 * kc + 1][0], sc[2 * kc + 1][1]);
            pa[3] = pack_f16x2(sc[2 * kc + 1][2], sc[2 * kc + 1][3]);
#pragma unroll
            for (int dp = 0; dp < 4; dp++) {
                uint32_t vf4[4];
                ldsm_x4_t(vf4, vbb + (uint32_t)(kc * 16 * AST + dp * 16) * 2);
                mma_f16(oacc[2 * dp],     pa, vf4[0], vf4[1]);
                mma_f16(oacc[2 * dp + 1], pa, vf4[2], vf4[3]);
            }
        }
    }

    // ---- normalize + write fp16 (att layout [4096, 768]) ----
    l0r += __shfl_xor_sync(0xffffffffu, l0r, 1);
    l0r += __shfl_xor_sync(0xffffffffu, l0r, 2);
    l1r += __shfl_xor_sync(0xffffffffu, l1r, 1);
    l1r += __shfl_xor_sync(0xffffffffu, l1r, 2);
    float i0 = 1.f / l0r, i1 = 1.f / l1r;
    int row = b * 1024 + n0 + wp * 16 + (lane >> 2);
    int colb = h * 64 + c0;
#pragma unroll
    for (int d = 0; d < 8; d++) {
        __half2 h0 = __floats2half2_rn(oacc[d][0] * i0, oacc[d][1] * i0);
        __half2 h1 = __floats2half2_rn(oacc[d][2] * i1, oacc[d][3] * i1);
        *(uint32_t*)(att16 + (size_t)row * 768 + colb + d * 8) = *(uint32_t*)&h0;
        *(uint32_t*)(att16 + (size_t)(row + 8) * 768 + colb + d * 8) = *(uint32_t*)&h1;
    }
}

// ===========================================================================
// Output projection: single-pass fp16 NT GEMM, fp32 + bias epilogue.
// Block tile 64x128 (384 CTAs: finer SM load balance), K-chunk 64, 3-stage,
// ONE barrier per chunk, 2 CTAs/SM. 8 warps = 2m x 4n, warp tile 32x32.
// ===========================================================================
#define OTA (64 * AST * 2)           // A array bytes/stage (9216)
#define OTB (128 * AST * 2)          // B array bytes/stage (18432)
#define OSTB (OTA + OTB)             // stage stride (27648)

__global__ __launch_bounds__(256, 2) void gemm_out(
    const __half* __restrict__ Af, const __half* __restrict__ Bf,
    const float* __restrict__ bias, float* __restrict__ Cf)
{
    extern __shared__ __align__(16) __half smh[];
    const uint32_t sb = smem_u32(smh);

    const int tid = threadIdx.x, wid = tid >> 5, lane = tid & 31;
    const int wm = (wid >> 2) * 32, wn = (wid & 3) * 32;
    const int m0 = blockIdx.y * 64, n0 = blockIdx.x * 128;

    const __half* gA = Af + (size_t)m0 * 768;
    const __half* gB = Bf + (size_t)n0 * 768;

    float acc[2][4][4];
#pragma unroll
    for (int i = 0; i < 2; i++)
#pragma unroll
        for (int j = 0; j < 4; j++)
#pragma unroll
            for (int k = 0; k < 4; k++) acc[i][j][k] = 0.f;

#define OSTAGE(buf, c_)                                                        \
    {                                                                          \
        uint32_t base_ = sb + (buf) * OSTB;                                    \
        const int k0_ = (c_) * 64;                                             \
        _Pragma("unroll")                                                      \
        for (int it = 0; it < 2; it++) {                                       \
            int idx = it * 256 + tid;                                          \
            int row = idx >> 3, cc = idx & 7;                                  \
            uint32_t off = (uint32_t)(row * AST + cc * 8) * 2;                 \
            cpa16(base_ + off, gA + (size_t)row * 768 + k0_ + cc * 8);         \
        }                                                                      \
        _Pragma("unroll")                                                      \
        for (int it = 0; it < 4; it++) {                                       \
            int idx = it * 256 + tid;                                          \
            int row = idx >> 3, cc = idx & 7;                                  \
            uint32_t off = (uint32_t)(row * AST + cc * 8) * 2;                 \
            cpa16(base_ + OTA + off, gB + (size_t)row * 768 + k0_ + cc * 8);   \
        }                                                                      \
        asm volatile("cp.async.commit_group;" ::: "memory");                   \
    }

    OSTAGE(0, 0); OSTAGE(1, 1);

    const int lrow = lane & 15, lcol8 = (lane >> 4) * 8;
    const uint32_t offA = (uint32_t)((wm + lrow) * AST + lcol8) * 2;
    const uint32_t offB = (uint32_t)((wn + lrow) * AST + lcol8) * 2;

    for (int c = 0; c < 12; c++) {
        if (c + 2 < 12) {
            asm volatile("cp.async.wait_group 1;" ::: "memory");
        } else {
            asm volatile("cp.async.wait_group 0;" ::: "memory");
        }
        __syncthreads();
        if (c + 2 < 12) OSTAGE((c + 2) % 3, c + 2);
        uint32_t base = sb + (c % 3) * OSTB;
        uint32_t aA = base + offA, aB = base + OTA + offB;
#pragma unroll
        for (int kk = 0; kk < 4; kk++) {
            const uint32_t koff = kk * 32;
            uint32_t af[2][4];
#pragma unroll
            for (int mf = 0; mf < 2; mf++)
                ldsm_x4(af[mf], aA + mf * 16 * AST * 2 + koff);
#pragma unroll
            for (int nq = 0; nq < 2; nq++) {
                uint32_t bq[4];
                ldsm_x4(bq, aB + nq * 16 * AST * 2 + koff);
#pragma unroll
                for (int mf = 0; mf < 2; mf++) {
                    mma_f16(acc[mf][nq * 2 + 0], af[mf], bq[0], bq[2]);
                    mma_f16(acc[mf][nq * 2 + 1], af[mf], bq[1], bq[3]);
                }
            }
        }
    }

#pragma unroll
    for (int mf = 0; mf < 2; mf++) {
#pragma unroll
        for (int nf = 0; nf < 4; nf++) {
            int row = m0 + wm + mf * 16 + (lane >> 2);
            int col = n0 + wn + nf * 8 + (lane & 3) * 2;
            float b0 = bias[col], b1 = bias[col + 1];
            *(float2*)(Cf + (size_t)row * 768 + col) =
                make_float2(acc[mf][nf][0] + b0, acc[mf][nf][1] + b1);
            *(float2*)(Cf + (size_t)(row + 8) * 768 + col) =
                make_float2(acc[mf][nf][2] + b0, acc[mf][nf][3] + b1);
        }
    }
}

// ===========================================================================
// Launch
// ===========================================================================
extern "C" void kernel_launch(void* const* d_in, const int* in_sizes, int n_in,
                              void* d_out, int out_size)
{
    const float* query = (const float*)d_in[0];
    const float* attw  = (const float*)d_in[1];
    const float* Wq    = (const float*)d_in[2];
    const float* Wk    = (const float*)d_in[3];
    const float* Wv    = (const float*)d_in[4];
    const float* Wo    = (const float*)d_in[5];
    const float* bo    = (const float*)d_in[6];
    float* out = (float*)d_out;

    __half *qf16, *wf16, *qk16, *vfp, *att16;
    cudaGetSymbolAddress((void**)&qf16, g_qf16);
    cudaGetSymbolAddress((void**)&wf16, g_wf16);
    cudaGetSymbolAddress((void**)&qk16, g_qk16);
    cudaGetSymbolAddress((void**)&vfp, g_vf);
    cudaGetSymbolAddress((void**)&att16, g_att16);

    const int proj_smem = 3 * FSTB;                // 110592 (2 CTAs/SM)
    cudaFuncSetAttribute(proj_qkv, cudaFuncAttributeMaxDynamicSharedMemorySize, proj_smem);
    const int attn_smem = 3 * STB;                 // 82944 (2 CTAs/SM)
    cudaFuncSetAttribute(attn_mma, cudaFuncAttributeMaxDynamicSharedMemorySize, attn_smem);
    const int out_smem = 3 * OSTB;                 // 82944 (2 CTAs/SM)
    cudaFuncSetAttribute(gemm_out, cudaFuncAttributeMaxDynamicSharedMemorySize, out_smem);

    // 1) All conversions (fp16) in one launch
    conv_all<<<5376, 256>>>((const float4*)query,
                            (const float4*)Wq, (const float4*)Wk,
                            (const float4*)Wv, (const float4*)Wo,
                            (uint2*)qf16, (uint2*)wf16);

    // 2) Q, K, V projections: single fp16 GEMM, z selects weight + output
    proj_qkv<<<dim3(6, 32, 3), 256, proj_smem>>>(qf16, wf16, qk16, vfp);

    // 3) Fused biased attention (fp16 QK + fp16 PV) -> att fp16
    attn_mma<<<dim3(8, 12, 4), 256, attn_smem>>>(qk16, vfp, attw, att16);

    // 4) Output projection (fp16, 64x128 tiles for balance) -> fp32 + bias
    gemm_out<<<dim3(6, 64), 256, out_smem>>>(att16, wf16 + 3 * (size_t)WELE, bo, out);
}